// round 9
// baseline (speedup 1.0000x reference)
#include <cuda_runtime.h>

#define BB   8
#define TT   2000
#define DD   64
#define NRES 2000
#define KPAD 2048
#define KQ   (KPAD/4)     // 512 float4 per row
#define MAXC 16           // max column slots per block
#define GRP  12           // blocks per barrier group
#define MAXG 16           // max groups (148/12 -> 13)

// ---------------- device scratch ---------------------------------------------
__device__ float    g_WresT[NRES * KPAD];        // [n][k], k zero-padded (16 MB)
__device__ float    g_U[TT * BB * NRES];         // [t][b][n]              (128 MB)
__device__ float    g_H[BB * TT * NRES];         // [b][t][n], pre-augmented
__device__ float    g_S[2 * BB * NRES];          // double-buffered state
__device__ unsigned g_barCnt = 0;                // legacy entry barrier
__device__ unsigned g_barGen = 0;
__device__ unsigned g_grpCnt[MAXG * 32];         // group counters, 128B apart
__device__ unsigned g_rootCnt = 0;
__device__ unsigned g_grpRel[MAXG * 32];         // group release words, 128B apart

// ---------------- legacy atomic barrier (entry only) -------------------------
__device__ __forceinline__ void entry_sync(unsigned nblk) {
    __threadfence();
    __syncthreads();
    if (threadIdx.x == 0) {
        volatile unsigned* genp = &g_barGen;
        unsigned gen = *genp;
        if (atomicInc(&g_barCnt, nblk - 1) == nblk - 1) {
            *genp = gen + 1;
        } else {
            while (*genp == gen) { __nanosleep(64); }
        }
    }
    __syncthreads();
}

// ---------------- tree barrier: group atomics -> root atomic -> group release
__device__ __forceinline__ void tree_sync(int nblk, int bid, unsigned gen) {
    __threadfence();          // order g_S/g_H writes before arrival
    __syncthreads();
    if (threadIdx.x == 0) {
        const int g     = bid / GRP;
        const int ngrp  = (nblk + GRP - 1) / GRP;
        const int gsize = (g == ngrp - 1) ? (nblk - g * GRP) : GRP;
        volatile unsigned* rel = &g_grpRel[g * 32];
        if (atomicInc(&g_grpCnt[g * 32], (unsigned)gsize - 1) == (unsigned)gsize - 1) {
            // last in group -> arrive at root
            if (atomicInc(&g_rootCnt, (unsigned)ngrp - 1) == (unsigned)ngrp - 1) {
                __threadfence();
                #pragma unroll 4
                for (int j = 0; j < ngrp; j++)
                    *(volatile unsigned*)&g_grpRel[j * 32] = gen;
            } else {
                while (*rel != gen) { }
            }
        } else {
            while (*rel != gen) { }
        }
    }
    __syncthreads();
}

// ---------------- Wres -> WresT (padded) -------------------------------------
__global__ void k_transpose(const float* __restrict__ Wres) {
    __shared__ float tile[32][33];
    int tx = threadIdx.x, ty = threadIdx.y;
    int k0 = blockIdx.x * 32;           // k tile (0..2047)
    int n0 = blockIdx.y * 32;           // n tile (0..1999)
    int k = k0 + ty, n = n0 + tx;
    float v = 0.f;
    if (k < NRES && n < NRES) v = Wres[k * NRES + n];
    tile[ty][tx] = v;
    __syncthreads();
    int nn = n0 + ty, kk = k0 + tx;
    if (nn < NRES) g_WresT[nn * KPAD + kk] = tile[tx][ty];
}

// ---------------- U[t][b][n] = sum_d x[b][t][d] * Win[d][n] ------------------
__global__ void k_u(const float* __restrict__ x, const float* __restrict__ Win) {
    __shared__ float xs[BB][DD];
    int t = blockIdx.x, tid = threadIdx.x;
    if (tid < BB * (DD / 4)) {
        int b = tid / (DD / 4), q = tid % (DD / 4);
        ((float4*)&xs[b][0])[q] = ((const float4*)(x + (size_t)(b * TT + t) * DD))[q];
    }
    __syncthreads();
    for (int n = tid; n < NRES; n += blockDim.x) {
        float acc[BB];
        #pragma unroll
        for (int b = 0; b < BB; b++) acc[b] = 0.f;
        #pragma unroll
        for (int d4 = 0; d4 < DD / 4; d4++) {
            float w0 = Win[(d4 * 4 + 0) * NRES + n];
            float w1 = Win[(d4 * 4 + 1) * NRES + n];
            float w2 = Win[(d4 * 4 + 2) * NRES + n];
            float w3 = Win[(d4 * 4 + 3) * NRES + n];
            #pragma unroll
            for (int b = 0; b < BB; b++) {
                float4 xv = *(const float4*)&xs[b][d4 * 4];
                acc[b] = fmaf(xv.x, w0, acc[b]);
                acc[b] = fmaf(xv.y, w1, acc[b]);
                acc[b] = fmaf(xv.z, w2, acc[b]);
                acc[b] = fmaf(xv.w, w3, acc[b]);
            }
        }
        #pragma unroll
        for (int b = 0; b < BB; b++) g_U[(size_t)(t * BB + b) * NRES + n] = acc[b];
    }
}

// ---------------- persistent recurrence kernel (proven R8 layout) ------------
__global__ void __launch_bounds__(256, 1) k_esn() {
    extern __shared__ float smem[];
    float* s_sh = smem;                 // BB * KPAD
    float* w_sh = smem + BB * KPAD;     // MAXC * KPAD
    __shared__ float p_sh[2][8][132];   // [kh][lane-slot][col*8+b]

    const int tid  = threadIdx.x;
    const int lane = tid & 31;
    const int warp = tid >> 5;
    const int nblk = gridDim.x;
    const int bid  = blockIdx.x;

    const int base = NRES / nblk, rem = NRES % nblk;
    const int c0    = bid * base + (bid < rem ? bid : rem);
    const int ncols = base + (bid < rem ? 1 : 0);   // <= 16

    // preload this block's WresT slice into smem (once)
    {
        float4*       w4  = (float4*)w_sh;
        const float4* gW4 = (const float4*)g_WresT;
        for (int i = tid; i < MAXC * KQ; i += blockDim.x) {
            int c = i >> 9;
            int q = i & (KQ - 1);
            float4 v = make_float4(0.f, 0.f, 0.f, 0.f);
            if (c < ncols) v = gW4[(size_t)(c0 + c) * KQ + q];
            w4[i] = v;
        }
    }

    // zero state buffer 0 (grid-strided)
    for (int i = bid * blockDim.x + tid; i < BB * NRES; i += nblk * blockDim.x)
        g_S[i] = 0.f;

    entry_sync(nblk);
    // stable generation base across graph replays (all rel words equal here)
    const unsigned genbase = *(volatile unsigned*)&g_grpRel[(bid / GRP) * 32];

    const int kh = warp >> 2;           // K-half: 0 or 1
    const int cs = warp & 3;            // column-slot group: 4 cols each

    const int  f_slot = tid >> 3;       // finalize: tid < 128
    const int  f_b    = tid & 7;
    const bool f_act  = (tid < MAXC * BB) && (f_slot < ncols);
    const int  f_col  = c0 + f_slot;

    const float4* wr0 = (const float4*)w_sh + (size_t)(cs * 4 + 0) * KQ;
    const float4* wr1 = (const float4*)w_sh + (size_t)(cs * 4 + 1) * KQ;
    const float4* wr2 = (const float4*)w_sh + (size_t)(cs * 4 + 2) * KQ;
    const float4* wr3 = (const float4*)w_sh + (size_t)(cs * 4 + 3) * KQ;
    const float4* sB  = (const float4*)s_sh;

    #pragma unroll 1
    for (int t = 0; t < TT; t++) {
        const int buf = t & 1;

        // prefetch this step's input-projection value
        float uval = 0.f;
        if (f_act) uval = __ldg(&g_U[(size_t)(t * BB + f_b) * NRES + f_col]);

        // stage S (L2) -> smem, zero-padded to 2048
        {
            const float* Sp = g_S + (size_t)buf * (BB * NRES);
            float4* s4 = (float4*)s_sh;
            for (int i = tid; i < BB * KQ; i += blockDim.x) {
                int b = i >> 9;
                int q = i & (KQ - 1);
                float4 v = make_float4(0.f, 0.f, 0.f, 0.f);
                if (q * 4 < NRES)
                    v = __ldcg((const float4*)(Sp + (size_t)b * NRES + q * 4));
                s4[(size_t)b * KQ + q] = v;
            }
        }
        __syncthreads();

        // 4 cols x 8 batch rows per warp, over this warp's K-half
        float acc[4][8];
        #pragma unroll
        for (int c = 0; c < 4; c++)
            #pragma unroll
            for (int b = 0; b < 8; b++) acc[c][b] = 0.f;

        #pragma unroll
        for (int it = 0; it < 8; it++) {
            const int kq = kh * 256 + it * 32 + lane;
            const float4 w0 = wr0[kq];
            const float4 w1 = wr1[kq];
            const float4 w2 = wr2[kq];
            const float4 w3 = wr3[kq];
            #pragma unroll
            for (int b = 0; b < 8; b++) {
                const float4 s = sB[(size_t)b * KQ + kq];
                acc[0][b] = fmaf(s.x, w0.x, acc[0][b]);
                acc[0][b] = fmaf(s.y, w0.y, acc[0][b]);
                acc[0][b] = fmaf(s.z, w0.z, acc[0][b]);
                acc[0][b] = fmaf(s.w, w0.w, acc[0][b]);
                acc[1][b] = fmaf(s.x, w1.x, acc[1][b]);
                acc[1][b] = fmaf(s.y, w1.y, acc[1][b]);
                acc[1][b] = fmaf(s.z, w1.z, acc[1][b]);
                acc[1][b] = fmaf(s.w, w1.w, acc[1][b]);
                acc[2][b] = fmaf(s.x, w2.x, acc[2][b]);
                acc[2][b] = fmaf(s.y, w2.y, acc[2][b]);
                acc[2][b] = fmaf(s.z, w2.z, acc[2][b]);
                acc[2][b] = fmaf(s.w, w2.w, acc[2][b]);
                acc[3][b] = fmaf(s.x, w3.x, acc[3][b]);
                acc[3][b] = fmaf(s.y, w3.y, acc[3][b]);
                acc[3][b] = fmaf(s.z, w3.z, acc[3][b]);
                acc[3][b] = fmaf(s.w, w3.w, acc[3][b]);
            }
        }

        // 2-level reduction: lanes {l, l^8, l^16, l^24} merged
        #pragma unroll
        for (int c = 0; c < 4; c++)
            #pragma unroll
            for (int b = 0; b < 8; b++) {
                float v = acc[c][b];
                v += __shfl_xor_sync(0xFFFFFFFFu, v, 16);
                v += __shfl_xor_sync(0xFFFFFFFFu, v, 8);
                acc[c][b] = v;
            }
        if (lane < 8) {
            #pragma unroll
            for (int c = 0; c < 4; c++)
                #pragma unroll
                for (int b = 0; b < 8; b++)
                    p_sh[kh][lane][(cs * 4 + c) * 8 + b] = acc[c][b];
        }
        __syncthreads();

        if (f_act) {
            const int idx = f_slot * 8 + f_b;
            float v = uval;
            #pragma unroll
            for (int s = 0; s < 8; s++)
                v += p_sh[0][s][idx] + p_sh[1][s][idx];
            float h = tanhf(v);
            const int nbuf = buf ^ 1;
            __stcg(&g_S[(size_t)nbuf * (BB * NRES) + (size_t)f_b * NRES + f_col], h);
            float ha = ((f_col & 1) == 0) ? h * h : h;   // pre-augment for k_out
            g_H[((size_t)f_b * TT + t) * NRES + f_col] = ha;
        }

        tree_sync(nblk, bid, genbase + 1 + (unsigned)t);
    }
}

// ---------------- readout: out[b][t][d] = Haug[b][t][:] @ Wout ---------------
#define OT   8
#define HSTR 2004
__global__ void __launch_bounds__(256, 2) k_out(const float* __restrict__ Wout,
                                                float* __restrict__ out) {
    extern __shared__ float hs[];            // [OT][HSTR]
    __shared__ float ps[4][64][OT];
    const int tid = threadIdx.x;
    const int b   = blockIdx.y;
    const int t0  = blockIdx.x * OT;

    for (int r = 0; r < OT; r++) {
        const float4* src = (const float4*)(g_H + ((size_t)b * TT + (t0 + r)) * NRES);
        float4*       dst = (float4*)(hs + r * HSTR);
        for (int i = tid; i < 500; i += 256) dst[i] = __ldcg(src + i);
    }
    __syncthreads();

    const int d  = tid & 63;
    const int nq = tid >> 6;                 // 0..3
    float acc[OT];
    #pragma unroll
    for (int r = 0; r < OT; r++) acc[r] = 0.f;

    for (int q = nq; q < 500; q += 4) {
        const int n = q * 4;
        const float w0 = __ldg(&Wout[(size_t)(n + 0) * DD + d]);
        const float w1 = __ldg(&Wout[(size_t)(n + 1) * DD + d]);
        const float w2 = __ldg(&Wout[(size_t)(n + 2) * DD + d]);
        const float w3 = __ldg(&Wout[(size_t)(n + 3) * DD + d]);
        #pragma unroll
        for (int r = 0; r < OT; r++) {
            const float4 h4 = *(const float4*)(hs + r * HSTR + n);
            acc[r] = fmaf(h4.x, w0, acc[r]);
            acc[r] = fmaf(h4.y, w1, acc[r]);
            acc[r] = fmaf(h4.z, w2, acc[r]);
            acc[r] = fmaf(h4.w, w3, acc[r]);
        }
    }
    #pragma unroll
    for (int r = 0; r < OT; r++) ps[nq][d][r] = acc[r];
    __syncthreads();

    for (int i = tid; i < 64 * OT; i += 256) {
        int dd = i >> 3, rr = i & (OT - 1);
        float v = ps[0][dd][rr] + ps[1][dd][rr] + ps[2][dd][rr] + ps[3][dd][rr];
        out[((size_t)b * TT + (t0 + rr)) * DD + dd] = v;
    }
}

// ---------------- launch ------------------------------------------------------
extern "C" void kernel_launch(void* const* d_in, const int* in_sizes, int n_in,
                              void* d_out, int out_size) {
    const float* x    = (const float*)d_in[0];
    const float* Win  = (const float*)d_in[1];
    const float* Wres = (const float*)d_in[2];
    const float* Wout = (const float*)d_in[3];
    float*       out  = (float*)d_out;

    int dev = 0;
    cudaGetDevice(&dev);
    int nsm = 148;
    cudaDeviceGetAttribute(&nsm, cudaDevAttrMultiProcessorCount, dev);
    int nblk = nsm < 148 ? nsm : 148;   // 1 block/SM, all resident
    if (nblk < 125) nblk = 125;         // 16-slot capacity guard
    if (nblk > GRP * MAXG) nblk = GRP * MAXG;

    const size_t smem_main = (size_t)(BB * KPAD + MAXC * KPAD) * sizeof(float); // 192 KB
    cudaFuncSetAttribute(k_esn, cudaFuncAttributeMaxDynamicSharedMemorySize, (int)smem_main);
    const size_t smem_out = (size_t)OT * HSTR * sizeof(float);                  // ~64 KB
    cudaFuncSetAttribute(k_out, cudaFuncAttributeMaxDynamicSharedMemorySize, (int)smem_out);

    k_transpose<<<dim3(KPAD / 32, (NRES + 31) / 32), dim3(32, 32)>>>(Wres);
    k_u<<<TT, 256>>>(x, Win);
    k_esn<<<nblk, 256, smem_main>>>();
    k_out<<<dim3(TT / OT, BB), 256, smem_out>>>(Wout, out);
}

// round 10
// speedup vs baseline: 1.1207x; 1.1207x over previous
#include <cuda_runtime.h>

#define BB   8
#define TT   2000
#define DD   64
#define NRES 2000
#define KPAD 2048
#define KQ   (KPAD/4)     // 512 float4 per row
#define MAXC 16           // max column slots per block
#define NBLK 125          // 125 * 16 = 2000: zero padded-column waste

// ---------------- device scratch ---------------------------------------------
__device__ float    g_WresT[NRES * KPAD];        // [n][k], k zero-padded (16 MB)
__device__ float    g_U[TT * BB * NRES];         // [t][b][n]              (128 MB)
__device__ float    g_H[BB * TT * NRES];         // [b][t][n], pre-augmented
__device__ float    g_S[2 * BB * NRES];          // double-buffered state
__device__ unsigned g_barCnt = 0;
__device__ unsigned g_barGen = 0;

// ---------------- software grid barrier (proven atomic version) --------------
__device__ __forceinline__ void grid_sync(unsigned nblk) {
    __threadfence();
    __syncthreads();
    if (threadIdx.x == 0) {
        volatile unsigned* genp = &g_barGen;
        unsigned gen = *genp;
        if (atomicInc(&g_barCnt, nblk - 1) == nblk - 1) {
            *genp = gen + 1;
        } else {
            while (*genp == gen) { __nanosleep(64); }
        }
    }
    __syncthreads();
}

// ---------------- Wres -> WresT (padded) -------------------------------------
__global__ void k_transpose(const float* __restrict__ Wres) {
    __shared__ float tile[32][33];
    int tx = threadIdx.x, ty = threadIdx.y;
    int k0 = blockIdx.x * 32;           // k tile (0..2047)
    int n0 = blockIdx.y * 32;           // n tile (0..1999)
    int k = k0 + ty, n = n0 + tx;
    float v = 0.f;
    if (k < NRES && n < NRES) v = Wres[k * NRES + n];
    tile[ty][tx] = v;
    __syncthreads();
    int nn = n0 + ty, kk = k0 + tx;
    if (nn < NRES) g_WresT[nn * KPAD + kk] = tile[tx][ty];
}

// ---------------- U[t][b][n] = sum_d x[b][t][d] * Win[d][n] ------------------
__global__ void k_u(const float* __restrict__ x, const float* __restrict__ Win) {
    __shared__ float xs[BB][DD];
    int t = blockIdx.x, tid = threadIdx.x;
    if (tid < BB * (DD / 4)) {
        int b = tid / (DD / 4), q = tid % (DD / 4);
        ((float4*)&xs[b][0])[q] = ((const float4*)(x + (size_t)(b * TT + t) * DD))[q];
    }
    __syncthreads();
    for (int n = tid; n < NRES; n += blockDim.x) {
        float acc[BB];
        #pragma unroll
        for (int b = 0; b < BB; b++) acc[b] = 0.f;
        #pragma unroll
        for (int d4 = 0; d4 < DD / 4; d4++) {
            float w0 = Win[(d4 * 4 + 0) * NRES + n];
            float w1 = Win[(d4 * 4 + 1) * NRES + n];
            float w2 = Win[(d4 * 4 + 2) * NRES + n];
            float w3 = Win[(d4 * 4 + 3) * NRES + n];
            #pragma unroll
            for (int b = 0; b < BB; b++) {
                float4 xv = *(const float4*)&xs[b][d4 * 4];
                acc[b] = fmaf(xv.x, w0, acc[b]);
                acc[b] = fmaf(xv.y, w1, acc[b]);
                acc[b] = fmaf(xv.z, w2, acc[b]);
                acc[b] = fmaf(xv.w, w3, acc[b]);
            }
        }
        #pragma unroll
        for (int b = 0; b < BB; b++) g_U[(size_t)(t * BB + b) * NRES + n] = acc[b];
    }
}

// ---------------- persistent recurrence kernel (proven R8 layout) ------------
__global__ void __launch_bounds__(256, 1) k_esn() {
    extern __shared__ float smem[];
    float* s_sh = smem;                 // BB * KPAD
    float* w_sh = smem + BB * KPAD;     // MAXC * KPAD
    __shared__ float p_sh[2][8][132];   // [kh][lane-slot][col*8+b]

    const int tid  = threadIdx.x;
    const int lane = tid & 31;
    const int warp = tid >> 5;
    const int nblk = gridDim.x;
    const int bid  = blockIdx.x;

    const int base = NRES / nblk, rem = NRES % nblk;
    const int c0    = bid * base + (bid < rem ? bid : rem);
    const int ncols = base + (bid < rem ? 1 : 0);   // == 16 at nblk=125

    // preload this block's WresT slice into smem (once)
    {
        float4*       w4  = (float4*)w_sh;
        const float4* gW4 = (const float4*)g_WresT;
        for (int i = tid; i < MAXC * KQ; i += blockDim.x) {
            int c = i >> 9;
            int q = i & (KQ - 1);
            float4 v = make_float4(0.f, 0.f, 0.f, 0.f);
            if (c < ncols) v = gW4[(size_t)(c0 + c) * KQ + q];
            w4[i] = v;
        }
    }

    // zero state buffer 0 (grid-strided)
    for (int i = bid * blockDim.x + tid; i < BB * NRES; i += nblk * blockDim.x)
        g_S[i] = 0.f;

    grid_sync(nblk);

    const int kh = warp >> 2;           // K-half: 0 or 1
    const int cs = warp & 3;            // column-slot group: 4 cols each

    const int  f_slot = tid >> 3;       // finalize: tid < 128
    const int  f_b    = tid & 7;
    const bool f_act  = (tid < MAXC * BB) && (f_slot < ncols);
    const int  f_col  = c0 + f_slot;

    const float4* wr0 = (const float4*)w_sh + (size_t)(cs * 4 + 0) * KQ;
    const float4* wr1 = (const float4*)w_sh + (size_t)(cs * 4 + 1) * KQ;
    const float4* wr2 = (const float4*)w_sh + (size_t)(cs * 4 + 2) * KQ;
    const float4* wr3 = (const float4*)w_sh + (size_t)(cs * 4 + 3) * KQ;
    const float4* sB  = (const float4*)s_sh;

    #pragma unroll 1
    for (int t = 0; t < TT; t++) {
        const int buf = t & 1;

        // prefetch this step's input-projection value
        float uval = 0.f;
        if (f_act) uval = __ldg(&g_U[(size_t)(t * BB + f_b) * NRES + f_col]);

        // stage S (L2) -> smem, zero-padded to 2048
        {
            const float* Sp = g_S + (size_t)buf * (BB * NRES);
            float4* s4 = (float4*)s_sh;
            for (int i = tid; i < BB * KQ; i += blockDim.x) {
                int b = i >> 9;
                int q = i & (KQ - 1);
                float4 v = make_float4(0.f, 0.f, 0.f, 0.f);
                if (q * 4 < NRES)
                    v = __ldcg((const float4*)(Sp + (size_t)b * NRES + q * 4));
                s4[(size_t)b * KQ + q] = v;
            }
        }
        __syncthreads();

        // 4 cols x 8 batch rows per warp, over this warp's K-half
        float acc[4][8];
        #pragma unroll
        for (int c = 0; c < 4; c++)
            #pragma unroll
            for (int b = 0; b < 8; b++) acc[c][b] = 0.f;

        #pragma unroll
        for (int it = 0; it < 8; it++) {
            const int kq = kh * 256 + it * 32 + lane;
            const float4 w0 = wr0[kq];
            const float4 w1 = wr1[kq];
            const float4 w2 = wr2[kq];
            const float4 w3 = wr3[kq];
            #pragma unroll
            for (int b = 0; b < 8; b++) {
                const float4 s = sB[(size_t)b * KQ + kq];
                acc[0][b] = fmaf(s.x, w0.x, acc[0][b]);
                acc[0][b] = fmaf(s.y, w0.y, acc[0][b]);
                acc[0][b] = fmaf(s.z, w0.z, acc[0][b]);
                acc[0][b] = fmaf(s.w, w0.w, acc[0][b]);
                acc[1][b] = fmaf(s.x, w1.x, acc[1][b]);
                acc[1][b] = fmaf(s.y, w1.y, acc[1][b]);
                acc[1][b] = fmaf(s.z, w1.z, acc[1][b]);
                acc[1][b] = fmaf(s.w, w1.w, acc[1][b]);
                acc[2][b] = fmaf(s.x, w2.x, acc[2][b]);
                acc[2][b] = fmaf(s.y, w2.y, acc[2][b]);
                acc[2][b] = fmaf(s.z, w2.z, acc[2][b]);
                acc[2][b] = fmaf(s.w, w2.w, acc[2][b]);
                acc[3][b] = fmaf(s.x, w3.x, acc[3][b]);
                acc[3][b] = fmaf(s.y, w3.y, acc[3][b]);
                acc[3][b] = fmaf(s.z, w3.z, acc[3][b]);
                acc[3][b] = fmaf(s.w, w3.w, acc[3][b]);
            }
        }

        // 2-level reduction: lanes {l, l^8, l^16, l^24} merged
        #pragma unroll
        for (int c = 0; c < 4; c++)
            #pragma unroll
            for (int b = 0; b < 8; b++) {
                float v = acc[c][b];
                v += __shfl_xor_sync(0xFFFFFFFFu, v, 16);
                v += __shfl_xor_sync(0xFFFFFFFFu, v, 8);
                acc[c][b] = v;
            }
        if (lane < 8) {
            #pragma unroll
            for (int c = 0; c < 4; c++)
                #pragma unroll
                for (int b = 0; b < 8; b++)
                    p_sh[kh][lane][(cs * 4 + c) * 8 + b] = acc[c][b];
        }
        __syncthreads();

        if (f_act) {
            const int idx = f_slot * 8 + f_b;
            float v = uval;
            #pragma unroll
            for (int s = 0; s < 8; s++)
                v += p_sh[0][s][idx] + p_sh[1][s][idx];
            float h = tanhf(v);
            const int nbuf = buf ^ 1;
            __stcg(&g_S[(size_t)nbuf * (BB * NRES) + (size_t)f_b * NRES + f_col], h);
            float ha = ((f_col & 1) == 0) ? h * h : h;   // pre-augment for k_out
            g_H[((size_t)f_b * TT + t) * NRES + f_col] = ha;
        }

        grid_sync(nblk);
    }
}

// ---------------- readout: out[b][t][d] = Haug[b][t][:] @ Wout ---------------
#define OT   8
#define HSTR 2004
__global__ void __launch_bounds__(256, 2) k_out(const float* __restrict__ Wout,
                                                float* __restrict__ out) {
    extern __shared__ float hs[];            // [OT][HSTR]
    __shared__ float ps[4][64][OT];
    const int tid = threadIdx.x;
    const int b   = blockIdx.y;
    const int t0  = blockIdx.x * OT;

    for (int r = 0; r < OT; r++) {
        const float4* src = (const float4*)(g_H + ((size_t)b * TT + (t0 + r)) * NRES);
        float4*       dst = (float4*)(hs + r * HSTR);
        for (int i = tid; i < 500; i += 256) dst[i] = __ldcg(src + i);
    }
    __syncthreads();

    const int d  = tid & 63;
    const int nq = tid >> 6;                 // 0..3
    float acc[OT];
    #pragma unroll
    for (int r = 0; r < OT; r++) acc[r] = 0.f;

    for (int q = nq; q < 500; q += 4) {
        const int n = q * 4;
        const float w0 = __ldg(&Wout[(size_t)(n + 0) * DD + d]);
        const float w1 = __ldg(&Wout[(size_t)(n + 1) * DD + d]);
        const float w2 = __ldg(&Wout[(size_t)(n + 2) * DD + d]);
        const float w3 = __ldg(&Wout[(size_t)(n + 3) * DD + d]);
        #pragma unroll
        for (int r = 0; r < OT; r++) {
            const float4 h4 = *(const float4*)(hs + r * HSTR + n);
            acc[r] = fmaf(h4.x, w0, acc[r]);
            acc[r] = fmaf(h4.y, w1, acc[r]);
            acc[r] = fmaf(h4.z, w2, acc[r]);
            acc[r] = fmaf(h4.w, w3, acc[r]);
        }
    }
    #pragma unroll
    for (int r = 0; r < OT; r++) ps[nq][d][r] = acc[r];
    __syncthreads();

    for (int i = tid; i < 64 * OT; i += 256) {
        int dd = i >> 3, rr = i & (OT - 1);
        float v = ps[0][dd][rr] + ps[1][dd][rr] + ps[2][dd][rr] + ps[3][dd][rr];
        out[((size_t)b * TT + (t0 + rr)) * DD + dd] = v;
    }
}

// ---------------- launch ------------------------------------------------------
extern "C" void kernel_launch(void* const* d_in, const int* in_sizes, int n_in,
                              void* d_out, int out_size) {
    const float* x    = (const float*)d_in[0];
    const float* Win  = (const float*)d_in[1];
    const float* Wres = (const float*)d_in[2];
    const float* Wout = (const float*)d_in[3];
    float*       out  = (float*)d_out;

    const int nblk = NBLK;              // 125 blocks x 16 real cols = 2000

    const size_t smem_main = (size_t)(BB * KPAD + MAXC * KPAD) * sizeof(float); // 192 KB
    cudaFuncSetAttribute(k_esn, cudaFuncAttributeMaxDynamicSharedMemorySize, (int)smem_main);
    const size_t smem_out = (size_t)OT * HSTR * sizeof(float);                  // ~64 KB
    cudaFuncSetAttribute(k_out, cudaFuncAttributeMaxDynamicSharedMemorySize, (int)smem_out);

    k_transpose<<<dim3(KPAD / 32, (NRES + 31) / 32), dim3(32, 32)>>>(Wres);
    k_u<<<TT, 256>>>(x, Win);
    k_esn<<<nblk, 256, smem_main>>>();
    k_out<<<dim3(TT / OT, BB), 256, smem_out>>>(Wout, out);
}

// round 11
// speedup vs baseline: 1.1213x; 1.0006x over previous
#include <cuda_runtime.h>
#include <cuda_bf16.h>

#define BB   8
#define TT   2000
#define DD   64
#define NRES 2000
#define KPAD 2048
#define MAXC 16
#define NBLK 125          // 125 * 16 = 2000 exactly

// smem byte offsets (dynamic smem): A=W fragments, B=S fragments
#define A_HI 0            // 8 warps * 8192 B
#define A_LO (A_HI + 65536)
#define B_HI (A_LO + 65536)   // 8 warps * 4096 B
#define B_LO (B_HI + 32768)
#define SMEM_MAIN (B_LO + 32768)   // 196608 B

// ---------------- device scratch ---------------------------------------------
__device__ float    g_WresT[NRES * KPAD];        // [n][k], k zero-padded (16 MB)
__device__ float    g_U[TT * BB * NRES];         // [t][b][n]              (128 MB)
__device__ float    g_H[BB * TT * NRES];         // [b][t][n], pre-augmented
__device__ unsigned g_Spack[2 * BB * KPAD];      // packed bf16 hi|lo state, K-padded
__device__ unsigned g_barCnt = 0;
__device__ unsigned g_barGen = 0;

// ---------------- software grid barrier (proven atomic version) --------------
__device__ __forceinline__ void grid_sync(unsigned nblk) {
    __threadfence();
    __syncthreads();
    if (threadIdx.x == 0) {
        volatile unsigned* genp = &g_barGen;
        unsigned gen = *genp;
        if (atomicInc(&g_barCnt, nblk - 1) == nblk - 1) {
            *genp = gen + 1;
        } else {
            while (*genp == gen) { __nanosleep(64); }
        }
    }
    __syncthreads();
}

#define MMA16816(c0, c1, c2, c3, a, b0, b1)                                   \
    asm volatile(                                                             \
        "mma.sync.aligned.m16n8k16.row.col.f32.bf16.bf16.f32 "                \
        "{%0,%1,%2,%3}, {%4,%5,%6,%7}, {%8,%9}, {%0,%1,%2,%3};"               \
        : "+f"(c0), "+f"(c1), "+f"(c2), "+f"(c3)                              \
        : "r"(a.x), "r"(a.y), "r"(a.z), "r"(a.w), "r"(b0), "r"(b1))

// ---------------- Wres -> WresT (padded) -------------------------------------
__global__ void k_transpose(const float* __restrict__ Wres) {
    __shared__ float tile[32][33];
    int tx = threadIdx.x, ty = threadIdx.y;
    int k0 = blockIdx.x * 32;
    int n0 = blockIdx.y * 32;
    int k = k0 + ty, n = n0 + tx;
    float v = 0.f;
    if (k < NRES && n < NRES) v = Wres[k * NRES + n];
    tile[ty][tx] = v;
    __syncthreads();
    int nn = n0 + ty, kk = k0 + tx;
    if (nn < NRES) g_WresT[nn * KPAD + kk] = tile[tx][ty];
}

// ---------------- U[t][b][n] = sum_d x[b][t][d] * Win[d][n] ------------------
__global__ void k_u(const float* __restrict__ x, const float* __restrict__ Win) {
    __shared__ float xs[BB][DD];
    int t = blockIdx.x, tid = threadIdx.x;
    if (tid < BB * (DD / 4)) {
        int b = tid / (DD / 4), q = tid % (DD / 4);
        ((float4*)&xs[b][0])[q] = ((const float4*)(x + (size_t)(b * TT + t) * DD))[q];
    }
    __syncthreads();
    for (int n = tid; n < NRES; n += blockDim.x) {
        float acc[BB];
        #pragma unroll
        for (int b = 0; b < BB; b++) acc[b] = 0.f;
        #pragma unroll
        for (int d4 = 0; d4 < DD / 4; d4++) {
            float w0 = Win[(d4 * 4 + 0) * NRES + n];
            float w1 = Win[(d4 * 4 + 1) * NRES + n];
            float w2 = Win[(d4 * 4 + 2) * NRES + n];
            float w3 = Win[(d4 * 4 + 3) * NRES + n];
            #pragma unroll
            for (int b = 0; b < BB; b++) {
                float4 xv = *(const float4*)&xs[b][d4 * 4];
                acc[b] = fmaf(xv.x, w0, acc[b]);
                acc[b] = fmaf(xv.y, w1, acc[b]);
                acc[b] = fmaf(xv.z, w2, acc[b]);
                acc[b] = fmaf(xv.w, w3, acc[b]);
            }
        }
        #pragma unroll
        for (int b = 0; b < BB; b++) g_U[(size_t)(t * BB + b) * NRES + n] = acc[b];
    }
}

// ---------------- persistent recurrence kernel: split-bf16 mma ---------------
// Per block: D[16 cols x 8 b] = W[16 x 2048] @ S[2048 x 8].
// Warp w owns K-slice [w*256, w*256+256): 16 iters of m16n8k16, 3 passes
// (Whi*Shi, Whi*Slo, Wlo*Shi) accumulated in fp32. Cross-warp reduce via p_sh.
__global__ void __launch_bounds__(256, 1) k_esn() {
    extern __shared__ char sm[];
    __shared__ float p_sh[8][136];

    const int tid  = threadIdx.x;
    const int lane = tid & 31;
    const int warp = tid >> 5;
    const int nblk = gridDim.x;
    const int bid  = blockIdx.x;

    const int c0    = bid * MAXC;       // nblk == 125: exact partition
    const int ncols = MAXC;

    // ---- one-time: build W fragments (hi/lo bf16, mma fragment order) ----
    for (int idx = tid; idx < MAXC * KPAD; idx += 256) {
        int c = idx >> 11;              // 0..15  (row m)
        int k = idx & 2047;
        float wv = g_WresT[(size_t)(c0 + c) * KPAD + k];   // zero-padded k>=2000
        __nv_bfloat16 hb = __float2bfloat16(wv);
        __nv_bfloat16 lb = __float2bfloat16(wv - __bfloat162float(hb));
        int w  = k >> 8;                // warp K-slice
        int i  = (k >> 4) & 15;         // k-iter
        int kk = k & 15;                // col within 16x16 A tile
        int ln = ((c & 7) << 2) | ((kk & 7) >> 1);         // gid*4 + tig
        int rg = (c >> 3) + ((kk >> 3) << 1);              // a0..a3
        int by = kk & 1;
        int off = w * 8192 + i * 512 + ln * 16 + rg * 4 + by * 2;
        *(__nv_bfloat16*)(sm + A_HI + off) = hb;
        *(__nv_bfloat16*)(sm + A_LO + off) = lb;
    }

    // zero packed state (both buffers, incl. K-pad; pad never written again)
    for (int i = bid * 256 + tid; i < 2 * BB * KPAD; i += nblk * 256)
        g_Spack[i] = 0u;

    grid_sync(nblk);

    const int f_slot = tid >> 3;        // finalize: tid < 128
    const int f_b    = tid & 7;
    const bool f_act = (tid < MAXC * BB);
    const int  f_col = c0 + f_slot;

    const char* Ah = sm + A_HI + warp * 8192;
    const char* Al = sm + A_LO + warp * 8192;
    const char* Bh = sm + B_HI + warp * 4096;
    const char* Bl = sm + B_LO + warp * 4096;

    #pragma unroll 1
    for (int t = 0; t < TT; t++) {
        const int buf = t & 1;

        // prefetch input-projection value
        float uval = 0.f;
        if (f_act) uval = __ldg(&g_U[(size_t)(t * BB + f_b) * NRES + f_col]);

        // ---- stage packed S -> B fragments (hi/lo split) ----
        {
            const uint4* Sp = (const uint4*)(g_Spack + buf * (BB * KPAD));
            #pragma unroll 4
            for (int j = 0; j < 16; j++) {
                int u = tid + j * 256;          // 0..4095; 4 k-elems each
                uint4 v = __ldcg(&Sp[u]);
                int b  = u >> 9;                // 512 uint4 per b row
                int k0 = (u & 511) << 2;
                int w  = k0 >> 8;
                int i  = (k0 >> 4) & 15;
                int kk = k0 & 15;               // 0,4,8,12
                int rg   = kk >> 3;
                int tig0 = (kk & 7) >> 1;       // 0 or 2
                unsigned hx = v.x & 0xFFFFu, lx = v.x >> 16;
                unsigned hy = v.y & 0xFFFFu, ly = v.y >> 16;
                unsigned hz = v.z & 0xFFFFu, lz = v.z >> 16;
                unsigned hw = v.w & 0xFFFFu, lw = v.w >> 16;
                int off = w * 4096 + i * 256 + rg * 128 + (b * 4 + tig0) * 4;
                *(uint2*)(sm + B_HI + off) = make_uint2(hx | (hy << 16), hz | (hw << 16));
                *(uint2*)(sm + B_LO + off) = make_uint2(lx | (ly << 16), lz | (lw << 16));
            }
        }
        __syncthreads();

        // ---- tensor-core GEMM over this warp's K-slice ----
        float d0 = 0.f, d1 = 0.f, d2 = 0.f, d3 = 0.f;
        #pragma unroll
        for (int i = 0; i < 16; i++) {
            const uint4 ah = *(const uint4*)(Ah + i * 512 + lane * 16);
            const uint4 al = *(const uint4*)(Al + i * 512 + lane * 16);
            const unsigned bh0 = *(const unsigned*)(Bh + i * 256 + lane * 4);
            const unsigned bh1 = *(const unsigned*)(Bh + i * 256 + 128 + lane * 4);
            const unsigned bl0 = *(const unsigned*)(Bl + i * 256 + lane * 4);
            const unsigned bl1 = *(const unsigned*)(Bl + i * 256 + 128 + lane * 4);
            MMA16816(d0, d1, d2, d3, ah, bh0, bh1);   // hi*hi
            MMA16816(d0, d1, d2, d3, ah, bl0, bl1);   // hi*lo
            MMA16816(d0, d1, d2, d3, al, bh0, bh1);   // lo*hi
        }

        // ---- store C fragments for cross-warp reduce ----
        {
            const int gid = lane >> 2, tig = lane & 3;
            *(float2*)&p_sh[warp][gid * 8 + tig * 2]       = make_float2(d0, d1);
            *(float2*)&p_sh[warp][(gid + 8) * 8 + tig * 2] = make_float2(d2, d3);
        }
        __syncthreads();

        // ---- finalize ----
        if (f_act) {
            float v = uval;
            #pragma unroll
            for (int w = 0; w < 8; w++) v += p_sh[w][tid];
            float h = tanhf(v);
            __nv_bfloat16 hb = __float2bfloat16(h);
            __nv_bfloat16 lb = __float2bfloat16(h - __bfloat162float(hb));
            unsigned pack = (unsigned)*(unsigned short*)&hb
                          | ((unsigned)*(unsigned short*)&lb << 16);
            const int nbuf = buf ^ 1;
            __stcg(&g_Spack[nbuf * (BB * KPAD) + f_b * KPAD + f_col], pack);
            float ha = ((f_col & 1) == 0) ? h * h : h;   // pre-augment for k_out
            g_H[((size_t)f_b * TT + t) * NRES + f_col] = ha;
        }

        grid_sync(nblk);
    }
}

// ---------------- readout: out[b][t][d] = Haug[b][t][:] @ Wout ---------------
#define OT   8
#define HSTR 2004
__global__ void __launch_bounds__(256, 2) k_out(const float* __restrict__ Wout,
                                                float* __restrict__ out) {
    extern __shared__ float hs[];            // [OT][HSTR]
    __shared__ float ps[4][64][OT];
    const int tid = threadIdx.x;
    const int b   = blockIdx.y;
    const int t0  = blockIdx.x * OT;

    for (int r = 0; r < OT; r++) {
        const float4* src = (const float4*)(g_H + ((size_t)b * TT + (t0 + r)) * NRES);
        float4*       dst = (float4*)(hs + r * HSTR);
        for (int i = tid; i < 500; i += 256) dst[i] = __ldcg(src + i);
    }
    __syncthreads();

    const int d  = tid & 63;
    const int nq = tid >> 6;
    float acc[OT];
    #pragma unroll
    for (int r = 0; r < OT; r++) acc[r] = 0.f;

    for (int q = nq; q < 500; q += 4) {
        const int n = q * 4;
        const float w0 = __ldg(&Wout[(size_t)(n + 0) * DD + d]);
        const float w1 = __ldg(&Wout[(size_t)(n + 1) * DD + d]);
        const float w2 = __ldg(&Wout[(size_t)(n + 2) * DD + d]);
        const float w3 = __ldg(&Wout[(size_t)(n + 3) * DD + d]);
        #pragma unroll
        for (int r = 0; r < OT; r++) {
            const float4 h4 = *(const float4*)(hs + r * HSTR + n);
            acc[r] = fmaf(h4.x, w0, acc[r]);
            acc[r] = fmaf(h4.y, w1, acc[r]);
            acc[r] = fmaf(h4.z, w2, acc[r]);
            acc[r] = fmaf(h4.w, w3, acc[r]);
        }
    }
    #pragma unroll
    for (int r = 0; r < OT; r++) ps[nq][d][r] = acc[r];
    __syncthreads();

    for (int i = tid; i < 64 * OT; i += 256) {
        int dd = i >> 3, rr = i & (OT - 1);
        float v = ps[0][dd][rr] + ps[1][dd][rr] + ps[2][dd][rr] + ps[3][dd][rr];
        out[((size_t)b * TT + (t0 + rr)) * DD + dd] = v;
    }
}

// ---------------- launch ------------------------------------------------------
extern "C" void kernel_launch(void* const* d_in, const int* in_sizes, int n_in,
                              void* d_out, int out_size) {
    const float* x    = (const float*)d_in[0];
    const float* Win  = (const float*)d_in[1];
    const float* Wres = (const float*)d_in[2];
    const float* Wout = (const float*)d_in[3];
    float*       out  = (float*)d_out;

    cudaFuncSetAttribute(k_esn, cudaFuncAttributeMaxDynamicSharedMemorySize, SMEM_MAIN);
    const size_t smem_out = (size_t)OT * HSTR * sizeof(float);
    cudaFuncSetAttribute(k_out, cudaFuncAttributeMaxDynamicSharedMemorySize, (int)smem_out);

    k_transpose<<<dim3(KPAD / 32, (NRES + 31) / 32), dim3(32, 32)>>>(Wres);
    k_u<<<TT, 256>>>(x, Win);
    k_esn<<<NBLK, 256, SMEM_MAIN>>>();
    k_out<<<dim3(TT / OT, BB), 256, smem_out>>>(Wout, out);
}

// round 12
// speedup vs baseline: 1.2556x; 1.1197x over previous
#include <cuda_runtime.h>
#include <cuda_bf16.h>

#define BB   8
#define TT   2000
#define DD   64
#define NRES 2000
#define KPAD 2048
#define MAXC 16
#define NBLK 125          // 125 * 16 = 2000 exactly

// smem byte offsets (dynamic smem): A=W fragments, B=S fragments
#define A_HI 0            // 8 warps * 8192 B
#define A_LO (A_HI + 65536)
#define B_HI (A_LO + 65536)   // 8 warps * 4096 B
#define B_LO (B_HI + 32768)
#define SMEM_MAIN (B_LO + 32768)   // 196608 B

// ---------------- device scratch ---------------------------------------------
__device__ float    g_WresT[NRES * KPAD];        // [n][k], k zero-padded (16 MB)
__device__ float    g_U[TT * BB * NRES];         // [t][b][n]              (128 MB)
__device__ float    g_H[BB * TT * NRES];         // [b][t][n], pre-augmented
__device__ unsigned g_Spack[2 * BB * KPAD];      // packed bf16 hi|lo state, K-padded
__device__ unsigned g_barCnt = 0;
__device__ unsigned g_barGen = 0;

// ---------------- software grid barrier (proven atomic version) --------------
__device__ __forceinline__ void grid_sync(unsigned nblk) {
    __threadfence();
    __syncthreads();
    if (threadIdx.x == 0) {
        volatile unsigned* genp = &g_barGen;
        unsigned gen = *genp;
        if (atomicInc(&g_barCnt, nblk - 1) == nblk - 1) {
            *genp = gen + 1;
        } else {
            while (*genp == gen) { __nanosleep(64); }
        }
    }
    __syncthreads();
}

#define MMA16816(c0, c1, c2, c3, a, b0, b1)                                   \
    asm volatile(                                                             \
        "mma.sync.aligned.m16n8k16.row.col.f32.bf16.bf16.f32 "                \
        "{%0,%1,%2,%3}, {%4,%5,%6,%7}, {%8,%9}, {%0,%1,%2,%3};"               \
        : "+f"(c0), "+f"(c1), "+f"(c2), "+f"(c3)                              \
        : "r"(a.x), "r"(a.y), "r"(a.z), "r"(a.w), "r"(b0), "r"(b1))

// ---------------- Wres -> WresT (padded) -------------------------------------
__global__ void k_transpose(const float* __restrict__ Wres) {
    __shared__ float tile[32][33];
    int tx = threadIdx.x, ty = threadIdx.y;
    int k0 = blockIdx.x * 32;
    int n0 = blockIdx.y * 32;
    int k = k0 + ty, n = n0 + tx;
    float v = 0.f;
    if (k < NRES && n < NRES) v = Wres[k * NRES + n];
    tile[ty][tx] = v;
    __syncthreads();
    int nn = n0 + ty, kk = k0 + tx;
    if (nn < NRES) g_WresT[nn * KPAD + kk] = tile[tx][ty];
}

// ---------------- U[t][b][n] = sum_d x[b][t][d] * Win[d][n] ------------------
__global__ void k_u(const float* __restrict__ x, const float* __restrict__ Win) {
    __shared__ float xs[BB][DD];
    int t = blockIdx.x, tid = threadIdx.x;
    if (tid < BB * (DD / 4)) {
        int b = tid / (DD / 4), q = tid % (DD / 4);
        ((float4*)&xs[b][0])[q] = ((const float4*)(x + (size_t)(b * TT + t) * DD))[q];
    }
    __syncthreads();
    for (int n = tid; n < NRES; n += blockDim.x) {
        float acc[BB];
        #pragma unroll
        for (int b = 0; b < BB; b++) acc[b] = 0.f;
        #pragma unroll
        for (int d4 = 0; d4 < DD / 4; d4++) {
            float w0 = Win[(d4 * 4 + 0) * NRES + n];
            float w1 = Win[(d4 * 4 + 1) * NRES + n];
            float w2 = Win[(d4 * 4 + 2) * NRES + n];
            float w3 = Win[(d4 * 4 + 3) * NRES + n];
            #pragma unroll
            for (int b = 0; b < BB; b++) {
                float4 xv = *(const float4*)&xs[b][d4 * 4];
                acc[b] = fmaf(xv.x, w0, acc[b]);
                acc[b] = fmaf(xv.y, w1, acc[b]);
                acc[b] = fmaf(xv.z, w2, acc[b]);
                acc[b] = fmaf(xv.w, w3, acc[b]);
            }
        }
        #pragma unroll
        for (int b = 0; b < BB; b++) g_U[(size_t)(t * BB + b) * NRES + n] = acc[b];
    }
}

// ---------------- persistent recurrence kernel: split-bf16 mma ---------------
// Per block: D[16 cols x 8 b] = W[16 x 2048] @ S[2048 x 8].
// Warp w owns K-slice [w*256, w*256+256): 16 iters of m16n8k16, 3 passes
// (Whi*Shi, Whi*Slo, Wlo*Shi). Staging iterates DEST-linearly: conflict-free
// STS, constant source stride (+128 uints / iter), PRMT hi/lo split.
__global__ void __launch_bounds__(256, 1) k_esn() {
    extern __shared__ char sm[];
    __shared__ float p_sh[8][136];

    const int tid  = threadIdx.x;
    const int lane = tid & 31;
    const int warp = tid >> 5;
    const int nblk = gridDim.x;
    const int bid  = blockIdx.x;

    const int c0 = bid * MAXC;          // nblk == 125: exact partition

    // ---- one-time: build W fragments (hi/lo bf16, mma fragment order) ----
    for (int idx = tid; idx < MAXC * KPAD; idx += 256) {
        int c = idx >> 11;              // 0..15  (row m)
        int k = idx & 2047;
        float wv = g_WresT[(size_t)(c0 + c) * KPAD + k];   // zero-padded k>=2000
        __nv_bfloat16 hb = __float2bfloat16(wv);
        __nv_bfloat16 lb = __float2bfloat16(wv - __bfloat162float(hb));
        int w  = k >> 8;                // warp K-slice
        int i  = (k >> 4) & 15;         // k-iter
        int kk = k & 15;                // col within 16x16 A tile
        int ln = ((c & 7) << 2) | ((kk & 7) >> 1);         // gid*4 + tig
        int rg = (c >> 3) + ((kk >> 3) << 1);              // a0..a3
        int by = kk & 1;
        int off = w * 8192 + i * 512 + ln * 16 + rg * 4 + by * 2;
        *(__nv_bfloat16*)(sm + A_HI + off) = hb;
        *(__nv_bfloat16*)(sm + A_LO + off) = lb;
    }

    // zero packed state (both buffers, incl. K-pad; pad never written again)
    for (int i = bid * 256 + tid; i < 2 * BB * KPAD; i += nblk * 256)
        g_Spack[i] = 0u;

    grid_sync(nblk);

    const int f_slot = tid >> 3;        // finalize: tid < 128
    const int f_b    = tid & 7;
    const bool f_act = (tid < MAXC * BB);
    const int  f_col = c0 + f_slot;

    const char* Ah = sm + A_HI + warp * 8192;
    const char* Al = sm + A_LO + warp * 8192;
    const char* Bh = sm + B_HI + warp * 4096;
    const char* Bl = sm + B_LO + warp * 4096;

    // staging constants: dest uint2 index m = tid + j*256
    // m = (w<<9)|(i<<5)|(rg<<4)|(b<<1)|tigpair; all but i constant over j
    const int st_b  = (tid >> 1) & 7;
    const int st_k0 = ((tid >> 5) << 4) | (((tid >> 4) & 1) << 3) | ((tid & 1) << 2);
    char* dHi = sm + B_HI + tid * 8;
    char* dLo = sm + B_LO + tid * 8;

    #pragma unroll 1
    for (int t = 0; t < TT; t++) {
        const int buf = t & 1;

        // prefetch input-projection value
        float uval = 0.f;
        if (f_act) uval = __ldg(&g_U[(size_t)(t * BB + f_b) * NRES + f_col]);

        // ---- stage packed S -> B fragments (dest-linear, conflict-free) ----
        {
            const unsigned* Sp = g_Spack + buf * (BB * KPAD) + st_b * KPAD + st_k0;
            #pragma unroll
            for (int j = 0; j < 16; j++) {
                uint4 v = __ldcg((const uint4*)(Sp + j * 128));
                unsigned hi0 = __byte_perm(v.x, v.y, 0x5410);
                unsigned lo0 = __byte_perm(v.x, v.y, 0x7632);
                unsigned hi1 = __byte_perm(v.z, v.w, 0x5410);
                unsigned lo1 = __byte_perm(v.z, v.w, 0x7632);
                *(uint2*)(dHi + j * 2048) = make_uint2(hi0, hi1);
                *(uint2*)(dLo + j * 2048) = make_uint2(lo0, lo1);
            }
        }
        __syncthreads();

        // ---- tensor-core GEMM over this warp's K-slice ----
        float d0 = 0.f, d1 = 0.f, d2 = 0.f, d3 = 0.f;
        #pragma unroll
        for (int i = 0; i < 16; i++) {
            const uint4 ah = *(const uint4*)(Ah + i * 512 + lane * 16);
            const uint4 al = *(const uint4*)(Al + i * 512 + lane * 16);
            const unsigned bh0 = *(const unsigned*)(Bh + i * 256 + lane * 4);
            const unsigned bh1 = *(const unsigned*)(Bh + i * 256 + 128 + lane * 4);
            const unsigned bl0 = *(const unsigned*)(Bl + i * 256 + lane * 4);
            const unsigned bl1 = *(const unsigned*)(Bl + i * 256 + 128 + lane * 4);
            MMA16816(d0, d1, d2, d3, ah, bh0, bh1);   // hi*hi
            MMA16816(d0, d1, d2, d3, ah, bl0, bl1);   // hi*lo
            MMA16816(d0, d1, d2, d3, al, bh0, bh1);   // lo*hi
        }

        // ---- store C fragments for cross-warp reduce ----
        {
            const int gid = lane >> 2, tig = lane & 3;
            *(float2*)&p_sh[warp][gid * 8 + tig * 2]       = make_float2(d0, d1);
            *(float2*)&p_sh[warp][(gid + 8) * 8 + tig * 2] = make_float2(d2, d3);
        }
        __syncthreads();

        // ---- finalize ----
        if (f_act) {
            float v = uval;
            #pragma unroll
            for (int w = 0; w < 8; w++) v += p_sh[w][tid];
            float h = tanhf(v);
            __nv_bfloat16 hb = __float2bfloat16(h);
            __nv_bfloat16 lb = __float2bfloat16(h - __bfloat162float(hb));
            unsigned pack = (unsigned)*(unsigned short*)&hb
                          | ((unsigned)*(unsigned short*)&lb << 16);
            const int nbuf = buf ^ 1;
            __stcg(&g_Spack[nbuf * (BB * KPAD) + f_b * KPAD + f_col], pack);
            float ha = ((f_col & 1) == 0) ? h * h : h;   // pre-augment for k_out
            g_H[((size_t)f_b * TT + t) * NRES + f_col] = ha;
        }

        grid_sync(nblk);
    }
}

// ---------------- readout: out[b][t][d] = Haug[b][t][:] @ Wout ---------------
#define OT   8
#define HSTR 2004
__global__ void __launch_bounds__(256, 2) k_out(const float* __restrict__ Wout,
                                                float* __restrict__ out) {
    extern __shared__ float hs[];            // [OT][HSTR]
    __shared__ float ps[4][64][OT];
    const int tid = threadIdx.x;
    const int b   = blockIdx.y;
    const int t0  = blockIdx.x * OT;

    for (int r = 0; r < OT; r++) {
        const float4* src = (const float4*)(g_H + ((size_t)b * TT + (t0 + r)) * NRES);
        float4*       dst = (float4*)(hs + r * HSTR);
        for (int i = tid; i < 500; i += 256) dst[i] = __ldcg(src + i);
    }
    __syncthreads();

    const int d  = tid & 63;
    const int nq = tid >> 6;
    float acc[OT];
    #pragma unroll
    for (int r = 0; r < OT; r++) acc[r] = 0.f;

    for (int q = nq; q < 500; q += 4) {
        const int n = q * 4;
        const float w0 = __ldg(&Wout[(size_t)(n + 0) * DD + d]);
        const float w1 = __ldg(&Wout[(size_t)(n + 1) * DD + d]);
        const float w2 = __ldg(&Wout[(size_t)(n + 2) * DD + d]);
        const float w3 = __ldg(&Wout[(size_t)(n + 3) * DD + d]);
        #pragma unroll
        for (int r = 0; r < OT; r++) {
            const float4 h4 = *(const float4*)(hs + r * HSTR + n);
            acc[r] = fmaf(h4.x, w0, acc[r]);
            acc[r] = fmaf(h4.y, w1, acc[r]);
            acc[r] = fmaf(h4.z, w2, acc[r]);
            acc[r] = fmaf(h4.w, w3, acc[r]);
        }
    }
    #pragma unroll
    for (int r = 0; r < OT; r++) ps[nq][d][r] = acc[r];
    __syncthreads();

    for (int i = tid; i < 64 * OT; i += 256) {
        int dd = i >> 3, rr = i & (OT - 1);
        float v = ps[0][dd][rr] + ps[1][dd][rr] + ps[2][dd][rr] + ps[3][dd][rr];
        out[((size_t)b * TT + (t0 + rr)) * DD + dd] = v;
    }
}

// ---------------- launch ------------------------------------------------------
extern "C" void kernel_launch(void* const* d_in, const int* in_sizes, int n_in,
                              void* d_out, int out_size) {
    const float* x    = (const float*)d_in[0];
    const float* Win  = (const float*)d_in[1];
    const float* Wres = (const float*)d_in[2];
    const float* Wout = (const float*)d_in[3];
    float*       out  = (float*)d_out;

    cudaFuncSetAttribute(k_esn, cudaFuncAttributeMaxDynamicSharedMemorySize, SMEM_MAIN);
    const size_t smem_out = (size_t)OT * HSTR * sizeof(float);
    cudaFuncSetAttribute(k_out, cudaFuncAttributeMaxDynamicSharedMemorySize, (int)smem_out);

    k_transpose<<<dim3(KPAD / 32, (NRES + 31) / 32), dim3(32, 32)>>>(Wres);
    k_u<<<TT, 256>>>(x, Win);
    k_esn<<<NBLK, 256, SMEM_MAIN>>>();
    k_out<<<dim3(TT / OT, BB), 256, smem_out>>>(Wout, out);
}

// round 13
// speedup vs baseline: 1.3000x; 1.0354x over previous
#include <cuda_runtime.h>
#include <cuda_bf16.h>

#define BB   8
#define TT   2000
#define DD   64
#define NRES 2000
#define KPAD 2048
#define MAXC 16
#define NBLK 125          // 125 * 16 = 2000 exactly

// smem byte offsets (dynamic smem): A=W fragments, B=S fragments
#define A_HI 0            // 8 warps * 8192 B
#define A_LO (A_HI + 65536)
#define B_HI (A_LO + 65536)   // 8 warps * 4096 B
#define B_LO (B_HI + 32768)
#define SMEM_MAIN (B_LO + 32768)   // 196608 B

// ---------------- device scratch ---------------------------------------------
__device__ float    g_WresT[NRES * KPAD];        // [n][k], k zero-padded (16 MB)
__device__ float    g_U[TT * BB * NRES];         // [t][b][n]              (128 MB)
__device__ float    g_H[BB * TT * NRES];         // [b][t][n], pre-augmented
__device__ unsigned g_Spack[2 * BB * KPAD];      // packed bf16 hi|lo state, K-padded
__device__ unsigned g_barCnt = 0;
__device__ unsigned g_barGen = 0;

// ---------------- software grid barrier: fence-once variant ------------------
// __syncthreads establishes cta-scope happens-before from all writers to
// thread 0; thread 0's single gpu-scope fence then releases those writes
// (cumulativity) before the atomic arrive. Saves 255 MEMBARs/block/step.
__device__ __forceinline__ void grid_sync(unsigned nblk) {
    __syncthreads();
    if (threadIdx.x == 0) {
        __threadfence();
        volatile unsigned* genp = &g_barGen;
        unsigned gen = *genp;
        if (atomicInc(&g_barCnt, nblk - 1) == nblk - 1) {
            *genp = gen + 1;
        } else {
            while (*genp == gen) { }
        }
    }
    __syncthreads();
}

#define MMA16816(c0, c1, c2, c3, a, b0, b1)                                   \
    asm volatile(                                                             \
        "mma.sync.aligned.m16n8k16.row.col.f32.bf16.bf16.f32 "                \
        "{%0,%1,%2,%3}, {%4,%5,%6,%7}, {%8,%9}, {%0,%1,%2,%3};"               \
        : "+f"(c0), "+f"(c1), "+f"(c2), "+f"(c3)                              \
        : "r"(a.x), "r"(a.y), "r"(a.z), "r"(a.w), "r"(b0), "r"(b1))

// ---------------- Wres -> WresT (padded) -------------------------------------
__global__ void k_transpose(const float* __restrict__ Wres) {
    __shared__ float tile[32][33];
    int tx = threadIdx.x, ty = threadIdx.y;
    int k0 = blockIdx.x * 32;
    int n0 = blockIdx.y * 32;
    int k = k0 + ty, n = n0 + tx;
    float v = 0.f;
    if (k < NRES && n < NRES) v = Wres[k * NRES + n];
    tile[ty][tx] = v;
    __syncthreads();
    int nn = n0 + ty, kk = k0 + tx;
    if (nn < NRES) g_WresT[nn * KPAD + kk] = tile[tx][ty];
}

// ---------------- U[t][b][n] = sum_d x[b][t][d] * Win[d][n] ------------------
__global__ void k_u(const float* __restrict__ x, const float* __restrict__ Win) {
    __shared__ float xs[BB][DD];
    int t = blockIdx.x, tid = threadIdx.x;
    if (tid < BB * (DD / 4)) {
        int b = tid / (DD / 4), q = tid % (DD / 4);
        ((float4*)&xs[b][0])[q] = ((const float4*)(x + (size_t)(b * TT + t) * DD))[q];
    }
    __syncthreads();
    for (int n = tid; n < NRES; n += blockDim.x) {
        float acc[BB];
        #pragma unroll
        for (int b = 0; b < BB; b++) acc[b] = 0.f;
        #pragma unroll
        for (int d4 = 0; d4 < DD / 4; d4++) {
            float w0 = Win[(d4 * 4 + 0) * NRES + n];
            float w1 = Win[(d4 * 4 + 1) * NRES + n];
            float w2 = Win[(d4 * 4 + 2) * NRES + n];
            float w3 = Win[(d4 * 4 + 3) * NRES + n];
            #pragma unroll
            for (int b = 0; b < BB; b++) {
                float4 xv = *(const float4*)&xs[b][d4 * 4];
                acc[b] = fmaf(xv.x, w0, acc[b]);
                acc[b] = fmaf(xv.y, w1, acc[b]);
                acc[b] = fmaf(xv.z, w2, acc[b]);
                acc[b] = fmaf(xv.w, w3, acc[b]);
            }
        }
        #pragma unroll
        for (int b = 0; b < BB; b++) g_U[(size_t)(t * BB + b) * NRES + n] = acc[b];
    }
}

// ---------------- persistent recurrence kernel: split-bf16 mma ---------------
// Per block: D[16 cols x 8 b] = W[16 x 2048] @ S[2048 x 8].
// Warp w owns K-slice [w*256, w*256+256): 16 iters of m16n8k16, 3 passes
// (Whi*Shi, Whi*Slo, Wlo*Shi). Staging iterates DEST-linearly: conflict-free
// STS, constant source stride (+128 uints / iter), PRMT hi/lo split.
__global__ void __launch_bounds__(256, 1) k_esn() {
    extern __shared__ char sm[];
    __shared__ float p_sh[8][136];

    const int tid  = threadIdx.x;
    const int lane = tid & 31;
    const int warp = tid >> 5;
    const int nblk = gridDim.x;
    const int bid  = blockIdx.x;

    const int c0 = bid * MAXC;          // nblk == 125: exact partition

    // ---- one-time: build W fragments (hi/lo bf16, mma fragment order) ----
    for (int idx = tid; idx < MAXC * KPAD; idx += 256) {
        int c = idx >> 11;              // 0..15  (row m)
        int k = idx & 2047;
        float wv = g_WresT[(size_t)(c0 + c) * KPAD + k];   // zero-padded k>=2000
        __nv_bfloat16 hb = __float2bfloat16(wv);
        __nv_bfloat16 lb = __float2bfloat16(wv - __bfloat162float(hb));
        int w  = k >> 8;                // warp K-slice
        int i  = (k >> 4) & 15;         // k-iter
        int kk = k & 15;                // col within 16x16 A tile
        int ln = ((c & 7) << 2) | ((kk & 7) >> 1);         // gid*4 + tig
        int rg = (c >> 3) + ((kk >> 3) << 1);              // a0..a3
        int by = kk & 1;
        int off = w * 8192 + i * 512 + ln * 16 + rg * 4 + by * 2;
        *(__nv_bfloat16*)(sm + A_HI + off) = hb;
        *(__nv_bfloat16*)(sm + A_LO + off) = lb;
    }

    // zero packed state (both buffers, incl. K-pad; pad never written again)
    for (int i = bid * 256 + tid; i < 2 * BB * KPAD; i += nblk * 256)
        g_Spack[i] = 0u;

    grid_sync(nblk);

    const int f_slot = tid >> 3;        // finalize: tid < 128
    const int f_b    = tid & 7;
    const bool f_act = (tid < MAXC * BB);
    const int  f_col = c0 + f_slot;

    const char* Ah = sm + A_HI + warp * 8192;
    const char* Al = sm + A_LO + warp * 8192;
    const char* Bh = sm + B_HI + warp * 4096;
    const char* Bl = sm + B_LO + warp * 4096;

    // staging constants: dest uint2 index m = tid + j*256
    // m = (w<<9)|(i<<5)|(rg<<4)|(b<<1)|tigpair; all but i constant over j
    const int st_b  = (tid >> 1) & 7;
    const int st_k0 = ((tid >> 5) << 4) | (((tid >> 4) & 1) << 3) | ((tid & 1) << 2);
    char* dHi = sm + B_HI + tid * 8;
    char* dLo = sm + B_LO + tid * 8;

    #pragma unroll 1
    for (int t = 0; t < TT; t++) {
        const int buf = t & 1;

        // prefetch input-projection value
        float uval = 0.f;
        if (f_act) uval = __ldg(&g_U[(size_t)(t * BB + f_b) * NRES + f_col]);

        // ---- stage packed S -> B fragments (dest-linear, conflict-free) ----
        {
            const unsigned* Sp = g_Spack + buf * (BB * KPAD) + st_b * KPAD + st_k0;
            #pragma unroll
            for (int j = 0; j < 16; j++) {
                uint4 v = __ldcg((const uint4*)(Sp + j * 128));
                unsigned hi0 = __byte_perm(v.x, v.y, 0x5410);
                unsigned lo0 = __byte_perm(v.x, v.y, 0x7632);
                unsigned hi1 = __byte_perm(v.z, v.w, 0x5410);
                unsigned lo1 = __byte_perm(v.z, v.w, 0x7632);
                *(uint2*)(dHi + j * 2048) = make_uint2(hi0, hi1);
                *(uint2*)(dLo + j * 2048) = make_uint2(lo0, lo1);
            }
        }
        __syncthreads();

        // ---- tensor-core GEMM over this warp's K-slice ----
        float d0 = 0.f, d1 = 0.f, d2 = 0.f, d3 = 0.f;
        #pragma unroll
        for (int i = 0; i < 16; i++) {
            const uint4 ah = *(const uint4*)(Ah + i * 512 + lane * 16);
            const uint4 al = *(const uint4*)(Al + i * 512 + lane * 16);
            const unsigned bh0 = *(const unsigned*)(Bh + i * 256 + lane * 4);
            const unsigned bh1 = *(const unsigned*)(Bh + i * 256 + 128 + lane * 4);
            const unsigned bl0 = *(const unsigned*)(Bl + i * 256 + lane * 4);
            const unsigned bl1 = *(const unsigned*)(Bl + i * 256 + 128 + lane * 4);
            MMA16816(d0, d1, d2, d3, ah, bh0, bh1);   // hi*hi
            MMA16816(d0, d1, d2, d3, ah, bl0, bl1);   // hi*lo
            MMA16816(d0, d1, d2, d3, al, bh0, bh1);   // lo*hi
        }

        // ---- store C fragments for cross-warp reduce ----
        {
            const int gid = lane >> 2, tig = lane & 3;
            *(float2*)&p_sh[warp][gid * 8 + tig * 2]       = make_float2(d0, d1);
            *(float2*)&p_sh[warp][(gid + 8) * 8 + tig * 2] = make_float2(d2, d3);
        }
        __syncthreads();

        // ---- finalize ----
        if (f_act) {
            float v = uval;
            #pragma unroll
            for (int w = 0; w < 8; w++) v += p_sh[w][tid];
            float h = tanhf(v);
            __nv_bfloat16 hb = __float2bfloat16(h);
            __nv_bfloat16 lb = __float2bfloat16(h - __bfloat162float(hb));
            unsigned pack = (unsigned)*(unsigned short*)&hb
                          | ((unsigned)*(unsigned short*)&lb << 16);
            const int nbuf = buf ^ 1;
            __stcg(&g_Spack[nbuf * (BB * KPAD) + f_b * KPAD + f_col], pack);
            float ha = ((f_col & 1) == 0) ? h * h : h;   // pre-augment for k_out
            g_H[((size_t)f_b * TT + t) * NRES + f_col] = ha;
        }

        grid_sync(nblk);
    }
}

// ---------------- readout: out[b][t][d] = Haug[b][t][:] @ Wout ---------------
#define OT   8
#define HSTR 2004
__global__ void __launch_bounds__(256, 2) k_out(const float* __restrict__ Wout,
                                                float* __restrict__ out) {
    extern __shared__ float hs[];            // [OT][HSTR]
    __shared__ float ps[4][64][OT];
    const int tid = threadIdx.x;
    const int b   = blockIdx.y;
    const int t0  = blockIdx.x * OT;

    for (int r = 0; r < OT; r++) {
        const float4* src = (const float4*)(g_H + ((size_t)b * TT + (t0 + r)) * NRES);
        float4*       dst = (float4*)(hs + r * HSTR);
        for (int i = tid; i < 500; i += 256) dst[i] = __ldcg(src + i);
    }
    __syncthreads();

    const int d  = tid & 63;
    const int nq = tid >> 6;
    float acc[OT];
    #pragma unroll
    for (int r = 0; r < OT; r++) acc[r] = 0.f;

    for (int q = nq; q < 500; q += 4) {
        const int n = q * 4;
        const float w0 = __ldg(&Wout[(size_t)(n + 0) * DD + d]);
        const float w1 = __ldg(&Wout[(size_t)(n + 1) * DD + d]);
        const float w2 = __ldg(&Wout[(size_t)(n + 2) * DD + d]);
        const float w3 = __ldg(&Wout[(size_t)(n + 3) * DD + d]);
        #pragma unroll
        for (int r = 0; r < OT; r++) {
            const float4 h4 = *(const float4*)(hs + r * HSTR + n);
            acc[r] = fmaf(h4.x, w0, acc[r]);
            acc[r] = fmaf(h4.y, w1, acc[r]);
            acc[r] = fmaf(h4.z, w2, acc[r]);
            acc[r] = fmaf(h4.w, w3, acc[r]);
        }
    }
    #pragma unroll
    for (int r = 0; r < OT; r++) ps[nq][d][r] = acc[r];
    __syncthreads();

    for (int i = tid; i < 64 * OT; i += 256) {
        int dd = i >> 3, rr = i & (OT - 1);
        float v = ps[0][dd][rr] + ps[1][dd][rr] + ps[2][dd][rr] + ps[3][dd][rr];
        out[((size_t)b * TT + (t0 + rr)) * DD + dd] = v;
    }
}

// ---------------- launch ------------------------------------------------------
extern "C" void kernel_launch(void* const* d_in, const int* in_sizes, int n_in,
                              void* d_out, int out_size) {
    const float* x    = (const float*)d_in[0];
    const float* Win  = (const float*)d_in[1];
    const float* Wres = (const float*)d_in[2];
    const float* Wout = (const float*)d_in[3];
    float*       out  = (float*)d_out;

    cudaFuncSetAttribute(k_esn, cudaFuncAttributeMaxDynamicSharedMemorySize, SMEM_MAIN);
    const size_t smem_out = (size_t)OT * HSTR * sizeof(float);
    cudaFuncSetAttribute(k_out, cudaFuncAttributeMaxDynamicSharedMemorySize, (int)smem_out);

    k_transpose<<<dim3(KPAD / 32, (NRES + 31) / 32), dim3(32, 32)>>>(Wres);
    k_u<<<TT, 256>>>(x, Win);
    k_esn<<<NBLK, 256, SMEM_MAIN>>>();
    k_out<<<dim3(TT / OT, BB), 256, smem_out>>>(Wout, out);
}

// round 14
// speedup vs baseline: 1.5167x; 1.1667x over previous
#include <cuda_runtime.h>
#include <cuda_bf16.h>

#define BB   8
#define TT   2000
#define DD   64
#define NRES 2000
#define KPAD 2048
#define MAXC 16
#define NBLK 125          // 125 * 16 = 2000 exactly

// smem byte offsets (dynamic smem): A=W fragments only (B loads go direct)
#define A_HI 0            // 8 warps * 8192 B
#define A_LO (A_HI + 65536)
#define SMEM_MAIN (A_LO + 65536)   // 131072 B

// ---------------- device scratch ---------------------------------------------
__device__ float    g_WresT[NRES * KPAD];        // [n][k], k zero-padded (16 MB)
__device__ float    g_U[TT * BB * NRES];         // [t][b][n]              (128 MB)
__device__ float    g_H[BB * TT * NRES];         // [b][t][n], pre-augmented
__device__ unsigned g_Spack[2 * BB * KPAD];      // packed bf16 hi|lo state, K-padded
__device__ unsigned g_barCnt = 0;
__device__ unsigned g_barGen = 0;

// ---------------- software grid barrier: fence-once variant ------------------
__device__ __forceinline__ void grid_sync(unsigned nblk) {
    __syncthreads();
    if (threadIdx.x == 0) {
        __threadfence();
        volatile unsigned* genp = &g_barGen;
        unsigned gen = *genp;
        if (atomicInc(&g_barCnt, nblk - 1) == nblk - 1) {
            *genp = gen + 1;
        } else {
            while (*genp == gen) { }
        }
    }
    __syncthreads();
}

#define MMA16816(c0, c1, c2, c3, a, b0, b1)                                   \
    asm volatile(                                                             \
        "mma.sync.aligned.m16n8k16.row.col.f32.bf16.bf16.f32 "                \
        "{%0,%1,%2,%3}, {%4,%5,%6,%7}, {%8,%9}, {%0,%1,%2,%3};"               \
        : "+f"(c0), "+f"(c1), "+f"(c2), "+f"(c3)                              \
        : "r"(a.x), "r"(a.y), "r"(a.z), "r"(a.w), "r"(b0), "r"(b1))

// ---------------- Wres -> WresT (padded) -------------------------------------
__global__ void k_transpose(const float* __restrict__ Wres) {
    __shared__ float tile[32][33];
    int tx = threadIdx.x, ty = threadIdx.y;
    int k0 = blockIdx.x * 32;
    int n0 = blockIdx.y * 32;
    int k = k0 + ty, n = n0 + tx;
    float v = 0.f;
    if (k < NRES && n < NRES) v = Wres[k * NRES + n];
    tile[ty][tx] = v;
    __syncthreads();
    int nn = n0 + ty, kk = k0 + tx;
    if (nn < NRES) g_WresT[nn * KPAD + kk] = tile[tx][ty];
}

// ---------------- U[t][b][n] = sum_d x[b][t][d] * Win[d][n] ------------------
__global__ void k_u(const float* __restrict__ x, const float* __restrict__ Win) {
    __shared__ float xs[BB][DD];
    int t = blockIdx.x, tid = threadIdx.x;
    if (tid < BB * (DD / 4)) {
        int b = tid / (DD / 4), q = tid % (DD / 4);
        ((float4*)&xs[b][0])[q] = ((const float4*)(x + (size_t)(b * TT + t) * DD))[q];
    }
    __syncthreads();
    for (int n = tid; n < NRES; n += blockDim.x) {
        float acc[BB];
        #pragma unroll
        for (int b = 0; b < BB; b++) acc[b] = 0.f;
        #pragma unroll
        for (int d4 = 0; d4 < DD / 4; d4++) {
            float w0 = Win[(d4 * 4 + 0) * NRES + n];
            float w1 = Win[(d4 * 4 + 1) * NRES + n];
            float w2 = Win[(d4 * 4 + 2) * NRES + n];
            float w3 = Win[(d4 * 4 + 3) * NRES + n];
            #pragma unroll
            for (int b = 0; b < BB; b++) {
                float4 xv = *(const float4*)&xs[b][d4 * 4];
                acc[b] = fmaf(xv.x, w0, acc[b]);
                acc[b] = fmaf(xv.y, w1, acc[b]);
                acc[b] = fmaf(xv.z, w2, acc[b]);
                acc[b] = fmaf(xv.w, w3, acc[b]);
            }
        }
        #pragma unroll
        for (int b = 0; b < BB; b++) g_U[(size_t)(t * BB + b) * NRES + n] = acc[b];
    }
}

// ---------------- persistent recurrence kernel: split-bf16 mma ---------------
// Per block: D[16 cols x 8 b] = W[16 x 2048] @ S[2048 x 8].
// Warp w owns K-slice [w*256, w*256+256): 16 iters of m16n8k16, 3 passes
// (Whi*Shi, Whi*Slo, Wlo*Shi). B (state) fragments are loaded DIRECTLY from
// L2 (g_Spack) into registers: no smem staging, no pre-MMA syncthreads.
__global__ void __launch_bounds__(256, 1) k_esn() {
    extern __shared__ char sm[];
    __shared__ float p_sh[8][136];

    const int tid  = threadIdx.x;
    const int lane = tid & 31;
    const int warp = tid >> 5;
    const int nblk = gridDim.x;
    const int bid  = blockIdx.x;

    const int c0 = bid * MAXC;          // nblk == 125: exact partition

    // ---- one-time: build W fragments (hi/lo bf16, mma fragment order) ----
    for (int idx = tid; idx < MAXC * KPAD; idx += 256) {
        int c = idx >> 11;              // 0..15  (row m)
        int k = idx & 2047;
        float wv = g_WresT[(size_t)(c0 + c) * KPAD + k];   // zero-padded k>=2000
        __nv_bfloat16 hb = __float2bfloat16(wv);
        __nv_bfloat16 lb = __float2bfloat16(wv - __bfloat162float(hb));
        int w  = k >> 8;                // warp K-slice
        int i  = (k >> 4) & 15;         // k-iter
        int kk = k & 15;                // col within 16x16 A tile
        int ln = ((c & 7) << 2) | ((kk & 7) >> 1);         // gid*4 + tig
        int rg = (c >> 3) + ((kk >> 3) << 1);              // a0..a3
        int by = kk & 1;
        int off = w * 8192 + i * 512 + ln * 16 + rg * 4 + by * 2;
        *(__nv_bfloat16*)(sm + A_HI + off) = hb;
        *(__nv_bfloat16*)(sm + A_LO + off) = lb;
    }

    // zero packed state (both buffers, incl. K-pad; pad never written again)
    for (int i = bid * 256 + tid; i < 2 * BB * KPAD; i += nblk * 256)
        g_Spack[i] = 0u;

    grid_sync(nblk);

    const int f_slot = tid >> 3;        // finalize: tid < 128
    const int f_b    = tid & 7;
    const bool f_act = (tid < MAXC * BB);
    const int  f_col = c0 + f_slot;

    const char* Ah = sm + A_HI + warp * 8192;
    const char* Al = sm + A_LO + warp * 8192;

    // direct-B addressing: thread (gid = lane>>2 -> batch, tig = lane&3 -> k)
    const int gid = lane >> 2;
    const int tig = lane & 3;
    const unsigned* Sbase = g_Spack + gid * KPAD + warp * 256 + tig * 2;

    #pragma unroll 1
    for (int t = 0; t < TT; t++) {
        const int buf = t & 1;

        // prefetch input-projection value
        float uval = 0.f;
        if (f_act) uval = __ldg(&g_U[(size_t)(t * BB + f_b) * NRES + f_col]);

        const unsigned* Sw = Sbase + buf * (BB * KPAD);

        // ---- tensor-core GEMM: B fragments straight from L2 ----
        float d0 = 0.f, d1 = 0.f, d2 = 0.f, d3 = 0.f;
        #pragma unroll
        for (int i = 0; i < 16; i++) {
            const uint2 vA = __ldcg((const uint2*)(Sw + i * 16));
            const uint2 vB = __ldcg((const uint2*)(Sw + i * 16 + 8));
            const unsigned bh0 = __byte_perm(vA.x, vA.y, 0x5410);
            const unsigned bl0 = __byte_perm(vA.x, vA.y, 0x7632);
            const unsigned bh1 = __byte_perm(vB.x, vB.y, 0x5410);
            const unsigned bl1 = __byte_perm(vB.x, vB.y, 0x7632);
            const uint4 ah = *(const uint4*)(Ah + i * 512 + lane * 16);
            const uint4 al = *(const uint4*)(Al + i * 512 + lane * 16);
            MMA16816(d0, d1, d2, d3, ah, bh0, bh1);   // hi*hi
            MMA16816(d0, d1, d2, d3, ah, bl0, bl1);   // hi*lo
            MMA16816(d0, d1, d2, d3, al, bh0, bh1);   // lo*hi
        }

        // ---- store C fragments for cross-warp reduce ----
        *(float2*)&p_sh[warp][gid * 8 + tig * 2]       = make_float2(d0, d1);
        *(float2*)&p_sh[warp][(gid + 8) * 8 + tig * 2] = make_float2(d2, d3);
        __syncthreads();

        // ---- finalize ----
        if (f_act) {
            float v = uval;
            #pragma unroll
            for (int w = 0; w < 8; w++) v += p_sh[w][tid];
            float h = tanhf(v);
            __nv_bfloat16 hb = __float2bfloat16(h);
            __nv_bfloat16 lb = __float2bfloat16(h - __bfloat162float(hb));
            unsigned pack = (unsigned)*(unsigned short*)&hb
                          | ((unsigned)*(unsigned short*)&lb << 16);
            const int nbuf = buf ^ 1;
            __stcg(&g_Spack[nbuf * (BB * KPAD) + f_b * KPAD + f_col], pack);
            float ha = ((f_col & 1) == 0) ? h * h : h;   // pre-augment for k_out
            g_H[((size_t)f_b * TT + t) * NRES + f_col] = ha;
        }

        grid_sync(nblk);
    }
}

// ---------------- readout: out[b][t][d] = Haug[b][t][:] @ Wout ---------------
#define OT   8
#define HSTR 2004
__global__ void __launch_bounds__(256, 2) k_out(const float* __restrict__ Wout,
                                                float* __restrict__ out) {
    extern __shared__ float hs[];            // [OT][HSTR]
    __shared__ float ps[4][64][OT];
    const int tid = threadIdx.x;
    const int b   = blockIdx.y;
    const int t0  = blockIdx.x * OT;

    for (int r = 0; r < OT; r++) {
        const float4* src = (const float4*)(g_H + ((size_t)b * TT + (t0 + r)) * NRES);
        float4*       dst = (float4*)(hs + r * HSTR);
        for (int i = tid; i < 500; i += 256) dst[i] = __ldcg(src + i);
    }
    __syncthreads();

    const int d  = tid & 63;
    const int nq = tid >> 6;
    float acc[OT];
    #pragma unroll
    for (int r = 0; r < OT; r++) acc[r] = 0.f;

    for (int q = nq; q < 500; q += 4) {
        const int n = q * 4;
        const float w0 = __ldg(&Wout[(size_t)(n + 0) * DD + d]);
        const float w1 = __ldg(&Wout[(size_t)(n + 1) * DD + d]);
        const float w2 = __ldg(&Wout[(size_t)(n + 2) * DD + d]);
        const float w3 = __ldg(&Wout[(size_t)(n + 3) * DD + d]);
        #pragma unroll
        for (int r = 0; r < OT; r++) {
            const float4 h4 = *(const float4*)(hs + r * HSTR + n);
            acc[r] = fmaf(h4.x, w0, acc[r]);
            acc[r] = fmaf(h4.y, w1, acc[r]);
            acc[r] = fmaf(h4.z, w2, acc[r]);
            acc[r] = fmaf(h4.w, w3, acc[r]);
        }
    }
    #pragma unroll
    for (int r = 0; r < OT; r++) ps[nq][d][r] = acc[r];
    __syncthreads();

    for (int i = tid; i < 64 * OT; i += 256) {
        int dd = i >> 3, rr = i & (OT - 1);
        float v = ps[0][dd][rr] + ps[1][dd][rr] + ps[2][dd][rr] + ps[3][dd][rr];
        out[((size_t)b * TT + (t0 + rr)) * DD + dd] = v;
    }
}

// ---------------- launch ------------------------------------------------------
extern "C" void kernel_launch(void* const* d_in, const int* in_sizes, int n_in,
                              void* d_out, int out_size) {
    const float* x    = (const float*)d_in[0];
    const float* Win  = (const float*)d_in[1];
    const float* Wres = (const float*)d_in[2];
    const float* Wout = (const float*)d_in[3];
    float*       out  = (float*)d_out;

    cudaFuncSetAttribute(k_esn, cudaFuncAttributeMaxDynamicSharedMemorySize, SMEM_MAIN);
    const size_t smem_out = (size_t)OT * HSTR * sizeof(float);
    cudaFuncSetAttribute(k_out, cudaFuncAttributeMaxDynamicSharedMemorySize, (int)smem_out);

    k_transpose<<<dim3(KPAD / 32, (NRES + 31) / 32), dim3(32, 32)>>>(Wres);
    k_u<<<TT, 256>>>(x, Win);
    k_esn<<<NBLK, 256, SMEM_MAIN>>>();
    k_out<<<dim3(TT / OT, BB), 256, smem_out>>>(Wout, out);
}

// round 16
// speedup vs baseline: 1.7030x; 1.1228x over previous
#include <cuda_runtime.h>
#include <cuda_bf16.h>

#define BB   8
#define TT   2000
#define DD   64
#define NRES 2000
#define KPAD 2048
#define MAXC 16
#define NBLK 125          // 125 * 16 = 2000 exactly

// smem byte offsets (dynamic smem): A=W fragments only (B loads go direct)
#define A_HI 0            // 8 warps * 8192 B
#define A_LO (A_HI + 65536)
#define SMEM_MAIN (A_LO + 65536)   // 131072 B

// ---------------- device scratch ---------------------------------------------
__device__ float    g_WresT[NRES * KPAD];        // [n][k], k zero-padded (16 MB)
__device__ float    g_U[TT * BB * NRES];         // [t][b][n]              (128 MB)
__device__ float    g_H[BB * TT * NRES];         // [b][t][n], pre-augmented
__device__ unsigned g_Spack[2 * BB * KPAD];      // packed bf16 hi|lo state, K-padded
__device__ unsigned g_barCnt = 0;
__device__ unsigned g_barGen = 0;
__device__ unsigned g_flag[NBLK * 32];           // per-block step flags, 128B apart

// ---------------- entry barrier (once per launch; fence-once variant) --------
__device__ __forceinline__ void entry_sync(unsigned nblk) {
    __syncthreads();
    if (threadIdx.x == 0) {
        __threadfence();
        volatile unsigned* genp = &g_barGen;
        unsigned gen = *genp;
        if (atomicInc(&g_barCnt, nblk - 1) == nblk - 1) {
            *genp = gen + 1;
        } else {
            while (*genp == gen) { }
        }
    }
    __syncthreads();
}

#define MMA16816(c0, c1, c2, c3, a, b0, b1)                                   \
    asm volatile(                                                             \
        "mma.sync.aligned.m16n8k16.row.col.f32.bf16.bf16.f32 "                \
        "{%0,%1,%2,%3}, {%4,%5,%6,%7}, {%8,%9}, {%0,%1,%2,%3};"               \
        : "+f"(c0), "+f"(c1), "+f"(c2), "+f"(c3)                              \
        : "r"(a.x), "r"(a.y), "r"(a.z), "r"(a.w), "r"(b0), "r"(b1))

// ---------------- Wres -> WresT (padded) -------------------------------------
__global__ void k_transpose(const float* __restrict__ Wres) {
    __shared__ float tile[32][33];
    int tx = threadIdx.x, ty = threadIdx.y;
    int k0 = blockIdx.x * 32;
    int n0 = blockIdx.y * 32;
    int k = k0 + ty, n = n0 + tx;
    float v = 0.f;
    if (k < NRES && n < NRES) v = Wres[k * NRES + n];
    tile[ty][tx] = v;
    __syncthreads();
    int nn = n0 + ty, kk = k0 + tx;
    if (nn < NRES) g_WresT[nn * KPAD + kk] = tile[tx][ty];
}

// ---------------- U[t][b][n] = sum_d x[b][t][d] * Win[d][n] ------------------
__global__ void k_u(const float* __restrict__ x, const float* __restrict__ Win) {
    __shared__ float xs[BB][DD];
    int t = blockIdx.x, tid = threadIdx.x;
    if (tid < BB * (DD / 4)) {
        int b = tid / (DD / 4), q = tid % (DD / 4);
        ((float4*)&xs[b][0])[q] = ((const float4*)(x + (size_t)(b * TT + t) * DD))[q];
    }
    __syncthreads();
    for (int n = tid; n < NRES; n += blockDim.x) {
        float acc[BB];
        #pragma unroll
        for (int b = 0; b < BB; b++) acc[b] = 0.f;
        #pragma unroll
        for (int d4 = 0; d4 < DD / 4; d4++) {
            float w0 = Win[(d4 * 4 + 0) * NRES + n];
            float w1 = Win[(d4 * 4 + 1) * NRES + n];
            float w2 = Win[(d4 * 4 + 2) * NRES + n];
            float w3 = Win[(d4 * 4 + 3) * NRES + n];
            #pragma unroll
            for (int b = 0; b < BB; b++) {
                float4 xv = *(const float4*)&xs[b][d4 * 4];
                acc[b] = fmaf(xv.x, w0, acc[b]);
                acc[b] = fmaf(xv.y, w1, acc[b]);
                acc[b] = fmaf(xv.z, w2, acc[b]);
                acc[b] = fmaf(xv.w, w3, acc[b]);
            }
        }
        #pragma unroll
        for (int b = 0; b < BB; b++) g_U[(size_t)(t * BB + b) * NRES + n] = acc[b];
    }
}

// ---------------- persistent recurrence kernel: split-bf16 mma ---------------
// Per block: D[16 cols x 8 b] = W[16 x 2048] @ S[2048 x 8].
// Sync = decentralized flags: each block's 8 warps jointly poll all 125
// producer flags (k >= 2000 is padding -> clamp phantom producers to 124).
// Skew bound 1 step => double buffering race-free.
__global__ void __launch_bounds__(256, 1) k_esn() {
    extern __shared__ char sm[];
    __shared__ float p_sh[8][136];

    const int tid  = threadIdx.x;
    const int lane = tid & 31;
    const int warp = tid >> 5;
    const int nblk = gridDim.x;
    const int bid  = blockIdx.x;

    const int c0 = bid * MAXC;          // nblk == 125: exact partition

    // ---- one-time: build W fragments (hi/lo bf16, mma fragment order) ----
    for (int idx = tid; idx < MAXC * KPAD; idx += 256) {
        int c = idx >> 11;              // 0..15  (row m)
        int k = idx & 2047;
        float wv = g_WresT[(size_t)(c0 + c) * KPAD + k];   // zero-padded k>=2000
        __nv_bfloat16 hb = __float2bfloat16(wv);
        __nv_bfloat16 lb = __float2bfloat16(wv - __bfloat162float(hb));
        int w  = k >> 8;                // warp K-slice
        int i  = (k >> 4) & 15;         // k-iter
        int kk = k & 15;                // col within 16x16 A tile
        int ln = ((c & 7) << 2) | ((kk & 7) >> 1);         // gid*4 + tig
        int rg = (c >> 3) + ((kk >> 3) << 1);              // a0..a3
        int by = kk & 1;
        int off = w * 8192 + i * 512 + ln * 16 + rg * 4 + by * 2;
        *(__nv_bfloat16*)(sm + A_HI + off) = hb;
        *(__nv_bfloat16*)(sm + A_LO + off) = lb;
    }

    // zero packed state (both buffers)
    for (int i = bid * 256 + tid; i < 2 * BB * KPAD; i += nblk * 256)
        g_Spack[i] = 0u;

    // monotone flag base (own flag; uniform across blocks and replays)
    const unsigned base = *(volatile unsigned*)&g_flag[bid * 32];

    entry_sync(nblk);

    const int f_slot = tid >> 3;        // finalize: tid < 128
    const int f_b    = tid & 7;
    const bool f_act = (tid < MAXC * BB);
    const int  f_col = c0 + f_slot;

    const char* Ah = sm + A_HI + warp * 8192;
    const char* Al = sm + A_LO + warp * 8192;

    // direct-B addressing: thread (gid = lane>>2 -> batch, tig = lane&3 -> k)
    const int gid = lane >> 2;
    const int tig = lane & 3;
    const unsigned* Sbase = g_Spack + gid * KPAD + warp * 256 + tig * 2;

    // producer flag this lane polls; clamp phantom producers (>=125) to 124
    int pid = warp * 16 + (lane & 15);
    if (pid > NBLK - 1) pid = NBLK - 1;
    volatile unsigned* pflag = &g_flag[pid * 32];

    #pragma unroll 1
    for (int t = 0; t < TT; t++) {
        const int buf = t & 1;

        // prefetch input-projection value (independent of flags)
        float uval = 0.f;
        if (f_act) uval = __ldg(&g_U[(size_t)(t * BB + f_b) * NRES + f_col]);

        // ---- per-warp producer wait ----
        if (t > 0) {
            const unsigned target = base + (unsigned)t;
            while (*pflag < target) { }
            __syncwarp();
        }

        const unsigned* Sw = Sbase + buf * (BB * KPAD);

        // ---- tensor-core GEMM: B fragments straight from L2 ----
        float d0 = 0.f, d1 = 0.f, d2 = 0.f, d3 = 0.f;
        #pragma unroll
        for (int i = 0; i < 16; i++) {
            const uint2 vA = __ldcg((const uint2*)(Sw + i * 16));
            const uint2 vB = __ldcg((const uint2*)(Sw + i * 16 + 8));
            const unsigned bh0 = __byte_perm(vA.x, vA.y, 0x5410);
            const unsigned bl0 = __byte_perm(vA.x, vA.y, 0x7632);
            const unsigned bh1 = __byte_perm(vB.x, vB.y, 0x5410);
            const unsigned bl1 = __byte_perm(vB.x, vB.y, 0x7632);
            const uint4 ah = *(const uint4*)(Ah + i * 512 + lane * 16);
            const uint4 al = *(const uint4*)(Al + i * 512 + lane * 16);
            MMA16816(d0, d1, d2, d3, ah, bh0, bh1);   // hi*hi
            MMA16816(d0, d1, d2, d3, ah, bl0, bl1);   // hi*lo
            MMA16816(d0, d1, d2, d3, al, bh0, bh1);   // lo*hi
        }

        // ---- store C fragments for cross-warp reduce ----
        *(float2*)&p_sh[warp][gid * 8 + tig * 2]       = make_float2(d0, d1);
        *(float2*)&p_sh[warp][(gid + 8) * 8 + tig * 2] = make_float2(d2, d3);
        __syncthreads();

        // ---- finalize: compute h, publish S(t+1) ----
        float ha = 0.f;
        if (f_act) {
            float v = uval;
            #pragma unroll
            for (int w = 0; w < 8; w++) v += p_sh[w][tid];
            float h = tanhf(v);
            __nv_bfloat16 hb = __float2bfloat16(h);
            __nv_bfloat16 lb = __float2bfloat16(h - __bfloat162float(hb));
            unsigned pack = (unsigned)*(unsigned short*)&hb
                          | ((unsigned)*(unsigned short*)&lb << 16);
            const int nbuf = buf ^ 1;
            __stcg(&g_Spack[nbuf * (BB * KPAD) + f_b * KPAD + f_col], pack);
            ha = ((f_col & 1) == 0) ? h * h : h;   // pre-augment for k_out
        }
        __syncthreads();          // all S(t+1) stores issued before the fence

        if (tid == 0) {
            __threadfence();      // S(t+1) visible before flag
            *(volatile unsigned*)&g_flag[bid * 32] = base + (unsigned)t + 1u;
        }

        // H store off the critical path (after flag publication)
        if (f_act)
            g_H[((size_t)f_b * TT + t) * NRES + f_col] = ha;
    }
}

// ---------------- readout: out[b][t][d] = Haug[b][t][:] @ Wout ---------------
#define OT   8
#define HSTR 2004
__global__ void __launch_bounds__(256, 2) k_out(const float* __restrict__ Wout,
                                                float* __restrict__ out) {
    extern __shared__ float hs[];            // [OT][HSTR]
    __shared__ float ps[4][64][OT];
    const int tid = threadIdx.x;
    const int b   = blockIdx.y;
    const int t0  = blockIdx.x * OT;

    for (int r = 0; r < OT; r++) {
        const float4* src = (const float4*)(g_H + ((size_t)b * TT + (t0 + r)) * NRES);
        float4*       dst = (float4*)(hs + r * HSTR);
        for (int i = tid; i < 500; i += 256) dst[i] = __ldcg(src + i);
    }
    __syncthreads();

    const int d  = tid & 63;
    const int nq = tid >> 6;
    float acc[OT];
    #pragma unroll
    for (int r = 0; r < OT; r++) acc[r] = 0.f;

    for (int q = nq; q < 500; q += 4) {
        const int n = q * 4;
        const float w0 = __ldg(&Wout[(size_t)(n + 0) * DD + d]);
        const float w1 = __ldg(&Wout[(size_t)(n + 1) * DD + d]);
        const float w2 = __ldg(&Wout[(size_t)(n + 2) * DD + d]);
        const float w3 = __ldg(&Wout[(size_t)(n + 3) * DD + d]);
        #pragma unroll
        for (int r = 0; r < OT; r++) {
            const float4 h4 = *(const float4*)(hs + r * HSTR + n);
            acc[r] = fmaf(h4.x, w0, acc[r]);
            acc[r] = fmaf(h4.y, w1, acc[r]);
            acc[r] = fmaf(h4.z, w2, acc[r]);
            acc[r] = fmaf(h4.w, w3, acc[r]);
        }
    }
    #pragma unroll
    for (int r = 0; r < OT; r++) ps[nq][d][r] = acc[r];
    __syncthreads();

    for (int i = tid; i < 64 * OT; i += 256) {
        int dd = i >> 3, rr = i & (OT - 1);
        float v = ps[0][dd][rr] + ps[1][dd][rr] + ps[2][dd][rr] + ps[3][dd][rr];
        out[((size_t)b * TT + (t0 + rr)) * DD + dd] = v;
    }
}

// ---------------- launch ------------------------------------------------------
extern "C" void kernel_launch(void* const* d_in, const int* in_sizes, int n_in,
                              void* d_out, int out_size) {
    const float* x    = (const float*)d_in[0];
    const float* Win  = (const float*)d_in[1];
    const float* Wres = (const float*)d_in[2];
    const float* Wout = (const float*)d_in[3];
    float*       out  = (float*)d_out;

    cudaFuncSetAttribute(k_esn, cudaFuncAttributeMaxDynamicSharedMemorySize, SMEM_MAIN);
    const size_t smem_out = (size_t)OT * HSTR * sizeof(float);
    cudaFuncSetAttribute(k_out, cudaFuncAttributeMaxDynamicSharedMemorySize, (int)smem_out);

    k_transpose<<<dim3(KPAD / 32, (NRES + 31) / 32), dim3(32, 32)>>>(Wres);
    k_u<<<TT, 256>>>(x, Win);
    k_esn<<<NBLK, 256, SMEM_MAIN>>>();
    k_out<<<dim3(TT / OT, BB), 256, smem_out>>>(Wout, out);
}

// round 17
// speedup vs baseline: 1.7105x; 1.0044x over previous
#include <cuda_runtime.h>
#include <cuda_bf16.h>
#include <cuda_fp16.h>

#define BB   8
#define TT   2000
#define DD   64
#define NRES 2000
#define KPAD 2048
#define MAXC 16
#define NBLK 125          // 125 * 16 = 2000 exactly

// smem byte offsets (dynamic smem): A=W fragments only (B loads go direct)
#define A_HI 0            // 8 warps * 8192 B
#define A_LO (A_HI + 65536)
#define SMEM_MAIN (A_LO + 65536)   // 131072 B

// ---------------- device scratch ---------------------------------------------
__device__ float    g_WresT[NRES * KPAD];        // [n][k], k zero-padded (16 MB)
__device__ float    g_U[TT * BB * NRES];         // [t][b][n]              (128 MB)
__device__ __half   g_Hh[(size_t)BB * TT * NRES];// [b][t][n], pre-augmented (64 MB)
__device__ unsigned g_Spack[2 * BB * KPAD];      // packed bf16 hi|lo state, K-padded
__device__ unsigned g_barCnt = 0;
__device__ unsigned g_barGen = 0;
__device__ unsigned g_flag[NBLK * 32];           // per-block step flags, 128B apart

// ---------------- entry barrier (once per launch; fence-once variant) --------
__device__ __forceinline__ void entry_sync(unsigned nblk) {
    __syncthreads();
    if (threadIdx.x == 0) {
        __threadfence();
        volatile unsigned* genp = &g_barGen;
        unsigned gen = *genp;
        if (atomicInc(&g_barCnt, nblk - 1) == nblk - 1) {
            *genp = gen + 1;
        } else {
            while (*genp == gen) { }
        }
    }
    __syncthreads();
}

#define MMA16816(c0, c1, c2, c3, a, b0, b1)                                   \
    asm volatile(                                                             \
        "mma.sync.aligned.m16n8k16.row.col.f32.bf16.bf16.f32 "                \
        "{%0,%1,%2,%3}, {%4,%5,%6,%7}, {%8,%9}, {%0,%1,%2,%3};"               \
        : "+f"(c0), "+f"(c1), "+f"(c2), "+f"(c3)                              \
        : "r"(a.x), "r"(a.y), "r"(a.z), "r"(a.w), "r"(b0), "r"(b1))

// ---------------- Wres -> WresT (padded) -------------------------------------
__global__ void k_transpose(const float* __restrict__ Wres) {
    __shared__ float tile[32][33];
    int tx = threadIdx.x, ty = threadIdx.y;
    int k0 = blockIdx.x * 32;
    int n0 = blockIdx.y * 32;
    int k = k0 + ty, n = n0 + tx;
    float v = 0.f;
    if (k < NRES && n < NRES) v = Wres[k * NRES + n];
    tile[ty][tx] = v;
    __syncthreads();
    int nn = n0 + ty, kk = k0 + tx;
    if (nn < NRES) g_WresT[nn * KPAD + kk] = tile[tx][ty];
}

// ---------------- U[t][b][n] = sum_d x[b][t][d] * Win[d][n] ------------------
__global__ void k_u(const float* __restrict__ x, const float* __restrict__ Win) {
    __shared__ float xs[BB][DD];
    int t = blockIdx.x, tid = threadIdx.x;
    if (tid < BB * (DD / 4)) {
        int b = tid / (DD / 4), q = tid % (DD / 4);
        ((float4*)&xs[b][0])[q] = ((const float4*)(x + (size_t)(b * TT + t) * DD))[q];
    }
    __syncthreads();
    for (int n = tid; n < NRES; n += blockDim.x) {
        float acc[BB];
        #pragma unroll
        for (int b = 0; b < BB; b++) acc[b] = 0.f;
        #pragma unroll
        for (int d4 = 0; d4 < DD / 4; d4++) {
            float w0 = Win[(d4 * 4 + 0) * NRES + n];
            float w1 = Win[(d4 * 4 + 1) * NRES + n];
            float w2 = Win[(d4 * 4 + 2) * NRES + n];
            float w3 = Win[(d4 * 4 + 3) * NRES + n];
            #pragma unroll
            for (int b = 0; b < BB; b++) {
                float4 xv = *(const float4*)&xs[b][d4 * 4];
                acc[b] = fmaf(xv.x, w0, acc[b]);
                acc[b] = fmaf(xv.y, w1, acc[b]);
                acc[b] = fmaf(xv.z, w2, acc[b]);
                acc[b] = fmaf(xv.w, w3, acc[b]);
            }
        }
        #pragma unroll
        for (int b = 0; b < BB; b++) g_U[(size_t)(t * BB + b) * NRES + n] = acc[b];
    }
}

// ---------------- persistent recurrence kernel: split-bf16 mma ---------------
// Sync = decentralized flags (proven R16). NEW: split tail — flag published
// after a 128-thread named barrier; warps 4-7 free-run into step t+1's poll
// and B loads while warps 0-3 finalize. p_sh double-buffered by t&1.
__global__ void __launch_bounds__(256, 1) k_esn() {
    extern __shared__ char sm[];
    __shared__ float p_sh[2][8][136];

    const int tid  = threadIdx.x;
    const int lane = tid & 31;
    const int warp = tid >> 5;
    const int nblk = gridDim.x;
    const int bid  = blockIdx.x;

    const int c0 = bid * MAXC;          // nblk == 125: exact partition

    // ---- one-time: build W fragments (hi/lo bf16, mma fragment order) ----
    for (int idx = tid; idx < MAXC * KPAD; idx += 256) {
        int c = idx >> 11;              // 0..15  (row m)
        int k = idx & 2047;
        float wv = g_WresT[(size_t)(c0 + c) * KPAD + k];   // zero-padded k>=2000
        __nv_bfloat16 hb = __float2bfloat16(wv);
        __nv_bfloat16 lb = __float2bfloat16(wv - __bfloat162float(hb));
        int w  = k >> 8;                // warp K-slice
        int i  = (k >> 4) & 15;         // k-iter
        int kk = k & 15;                // col within 16x16 A tile
        int ln = ((c & 7) << 2) | ((kk & 7) >> 1);         // gid*4 + tig
        int rg = (c >> 3) + ((kk >> 3) << 1);              // a0..a3
        int by = kk & 1;
        int off = w * 8192 + i * 512 + ln * 16 + rg * 4 + by * 2;
        *(__nv_bfloat16*)(sm + A_HI + off) = hb;
        *(__nv_bfloat16*)(sm + A_LO + off) = lb;
    }

    // zero packed state (both buffers)
    for (int i = bid * 256 + tid; i < 2 * BB * KPAD; i += nblk * 256)
        g_Spack[i] = 0u;

    // monotone flag base (own flag; uniform across blocks and replays)
    const unsigned base = *(volatile unsigned*)&g_flag[bid * 32];

    entry_sync(nblk);

    const int f_b   = tid & 7;          // finalize: tid < 128
    const int f_col = c0 + (tid >> 3);

    const char* Ah = sm + A_HI + warp * 8192;
    const char* Al = sm + A_LO + warp * 8192;

    // direct-B addressing: thread (gid = lane>>2 -> batch, tig = lane&3 -> k)
    const int gid = lane >> 2;
    const int tig = lane & 3;
    const unsigned* Sbase = g_Spack + gid * KPAD + warp * 256 + tig * 2;

    // producer flag this lane polls; clamp phantom producers (>=125) to 124
    int pid = warp * 16 + (lane & 15);
    if (pid > NBLK - 1) pid = NBLK - 1;
    volatile unsigned* pflag = &g_flag[pid * 32];

    #pragma unroll 1
    for (int t = 0; t < TT; t++) {
        const int buf = t & 1;

        // prefetch input-projection value (independent of flags)
        float uval = 0.f;
        if (tid < 128) uval = __ldg(&g_U[(size_t)(t * BB + f_b) * NRES + f_col]);

        // ---- per-warp producer wait ----
        if (t > 0) {
            const unsigned target = base + (unsigned)t;
            while (*pflag < target) { }
            __syncwarp();
        }

        const unsigned* Sw = Sbase + buf * (BB * KPAD);

        // ---- tensor-core GEMM: B fragments straight from L2 ----
        float d0 = 0.f, d1 = 0.f, d2 = 0.f, d3 = 0.f;
        #pragma unroll
        for (int i = 0; i < 16; i++) {
            const uint2 vA = __ldcg((const uint2*)(Sw + i * 16));
            const uint2 vB = __ldcg((const uint2*)(Sw + i * 16 + 8));
            const unsigned bh0 = __byte_perm(vA.x, vA.y, 0x5410);
            const unsigned bl0 = __byte_perm(vA.x, vA.y, 0x7632);
            const unsigned bh1 = __byte_perm(vB.x, vB.y, 0x5410);
            const unsigned bl1 = __byte_perm(vB.x, vB.y, 0x7632);
            const uint4 ah = *(const uint4*)(Ah + i * 512 + lane * 16);
            const uint4 al = *(const uint4*)(Al + i * 512 + lane * 16);
            MMA16816(d0, d1, d2, d3, ah, bh0, bh1);   // hi*hi
            MMA16816(d0, d1, d2, d3, ah, bl0, bl1);   // hi*lo
            MMA16816(d0, d1, d2, d3, al, bh0, bh1);   // lo*hi
        }

        // ---- store C fragments (double-buffered) ----
        *(float2*)&p_sh[buf][warp][gid * 8 + tig * 2]       = make_float2(d0, d1);
        *(float2*)&p_sh[buf][warp][(gid + 8) * 8 + tig * 2] = make_float2(d2, d3);
        __syncthreads();                 // barrier 0: p_sh[buf] complete

        // ---- finalize (warps 0-3 only); warps 4-7 free-run to t+1 ----
        if (tid < 128) {
            float v = uval;
            #pragma unroll
            for (int w = 0; w < 8; w++) v += p_sh[buf][w][tid];
            float h = tanhf(v);
            __nv_bfloat16 hb = __float2bfloat16(h);
            __nv_bfloat16 lb = __float2bfloat16(h - __bfloat162float(hb));
            unsigned pack = (unsigned)*(unsigned short*)&hb
                          | ((unsigned)*(unsigned short*)&lb << 16);
            __stcg(&g_Spack[(buf ^ 1) * (BB * KPAD) + f_b * KPAD + f_col], pack);
            float ha = ((f_col & 1) == 0) ? h * h : h;   // pre-augment

            asm volatile("bar.sync 1, 128;" ::: "memory");   // finalize warps only
            if (tid == 0) {
                __threadfence();      // S(t+1) visible before flag
                *(volatile unsigned*)&g_flag[bid * 32] = base + (unsigned)t + 1u;
            }
            // H store off the critical path (after flag publication)
            g_Hh[((size_t)f_b * TT + t) * NRES + f_col] = __float2half(ha);
        }
    }
}

// ---------------- readout: out[b][t][d] = Haug[b][t][:] @ Wout ---------------
#define OT   8
#define HSTR 2004
__global__ void __launch_bounds__(256, 2) k_out(const float* __restrict__ Wout,
                                                float* __restrict__ out) {
    extern __shared__ float hs[];            // [OT][HSTR]
    __shared__ float ps[4][64][OT];
    const int tid = threadIdx.x;
    const int b   = blockIdx.y;
    const int t0  = blockIdx.x * OT;

    for (int r = 0; r < OT; r++) {
        const uint4* src = (const uint4*)(g_Hh + ((size_t)b * TT + (t0 + r)) * NRES);
        float* dst = hs + r * HSTR;
        for (int i = tid; i < 250; i += 256) {    // 250 uint4 = 2000 halves
            uint4 v = __ldcg(src + i);
            const __half2* hp = (const __half2*)&v;
            float2 f0 = __half22float2(hp[0]);
            float2 f1 = __half22float2(hp[1]);
            float2 f2 = __half22float2(hp[2]);
            float2 f3 = __half22float2(hp[3]);
            float4* d4 = (float4*)(dst + i * 8);
            d4[0] = make_float4(f0.x, f0.y, f1.x, f1.y);
            d4[1] = make_float4(f2.x, f2.y, f3.x, f3.y);
        }
    }
    __syncthreads();

    const int d  = tid & 63;
    const int nq = tid >> 6;
    float acc[OT];
    #pragma unroll
    for (int r = 0; r < OT; r++) acc[r] = 0.f;

    for (int q = nq; q < 500; q += 4) {
        const int n = q * 4;
        const float w0 = __ldg(&Wout[(size_t)(n + 0) * DD + d]);
        const float w1 = __ldg(&Wout[(size_t)(n + 1) * DD + d]);
        const float w2 = __ldg(&Wout[(size_t)(n + 2) * DD + d]);
        const float w3 = __ldg(&Wout[(size_t)(n + 3) * DD + d]);
        #pragma unroll
        for (int r = 0; r < OT; r++) {
            const float4 h4 = *(const float4*)(hs + r * HSTR + n);
            acc[r] = fmaf(h4.x, w0, acc[r]);
            acc[r] = fmaf(h4.y, w1, acc[r]);
            acc[r] = fmaf(h4.z, w2, acc[r]);
            acc[r] = fmaf(h4.w, w3, acc[r]);
        }
    }
    #pragma unroll
    for (int r = 0; r < OT; r++) ps[nq][d][r] = acc[r];
    __syncthreads();

    for (int i = tid; i < 64 * OT; i += 256) {
        int dd = i >> 3, rr = i & (OT - 1);
        float v = ps[0][dd][rr] + ps[1][dd][rr] + ps[2][dd][rr] + ps[3][dd][rr];
        out[((size_t)b * TT + (t0 + rr)) * DD + dd] = v;
    }
}

// ---------------- launch ------------------------------------------------------
extern "C" void kernel_launch(void* const* d_in, const int* in_sizes, int n_in,
                              void* d_out, int out_size) {
    const float* x    = (const float*)d_in[0];
    const float* Win  = (const float*)d_in[1];
    const float* Wres = (const float*)d_in[2];
    const float* Wout = (const float*)d_in[3];
    float*       out  = (float*)d_out;

    cudaFuncSetAttribute(k_esn, cudaFuncAttributeMaxDynamicSharedMemorySize, SMEM_MAIN);
    const size_t smem_out = (size_t)OT * HSTR * sizeof(float);
    cudaFuncSetAttribute(k_out, cudaFuncAttributeMaxDynamicSharedMemorySize, (int)smem_out);

    k_transpose<<<dim3(KPAD / 32, (NRES + 31) / 32), dim3(32, 32)>>>(Wres);
    k_u<<<TT, 256>>>(x, Win);
    k_esn<<<NBLK, 256, SMEM_MAIN>>>();
    k_out<<<dim3(TT / OT, BB), 256, smem_out>>>(Wout, out);
}